// round 1
// baseline (speedup 1.0000x reference)
#include <cuda_runtime.h>
#include <math.h>

// Shapes are fixed by the problem: B=2, S=2048, E=1024, H=16, D=64.
#define EMBED   1024
#define NHEADS  16
#define HDIM    64
#define MAXROWS 4096   // B*S

// Scratch buffers (no cudaMalloc allowed) — [B,S,E] layout, head h at col h*64.
__device__ float g_q  [MAXROWS * EMBED];
__device__ float g_k  [MAXROWS * EMBED];
__device__ float g_v  [MAXROWS * EMBED];
__device__ float g_ctx[MAXROWS * EMBED];

// ---------------------------------------------------------------------------
// NT SGEMM:  C[m,n] = sum_k A[m,k] * W[n,k] + bias[n]
// A: [M,K] row-major, W: [N,K] row-major (torch Linear weight), both K-contig.
// Tiles: 64x64 per block, BK=32, 256 threads, 4x4 register tile per thread.
// smem stored transposed ([k][m]) with +4 pad so the inner loop is
// 2x LDS.128 (one broadcast) + 16 FFMA per k.
// ---------------------------------------------------------------------------
__global__ __launch_bounds__(256) void gemm_nt_bias(
    const float* __restrict__ A, const float* __restrict__ W,
    const float* __restrict__ bias, float* __restrict__ C,
    int M, int N, int K)
{
    __shared__ float sA[32][68];
    __shared__ float sB[32][68];

    const int tid = threadIdx.x;
    const int tx  = tid & 15;
    const int ty  = tid >> 4;
    const int bm  = blockIdx.x * 64;
    const int bn  = blockIdx.y * 64;

    float acc[4][4] = {};

    for (int k0 = 0; k0 < K; k0 += 32) {
        // Load 64x32 A-tile and 64x32 W-tile (transposed into smem).
        #pragma unroll
        for (int i = 0; i < 2; i++) {
            int idx = tid + i * 256;          // 0..511 float4 slots
            int row = idx >> 3;               // 0..63
            int c4  = (idx & 7) << 2;         // 0,4,...,28
            float4 va = *(const float4*)(A + (size_t)(bm + row) * K + k0 + c4);
            sA[c4 + 0][row] = va.x;
            sA[c4 + 1][row] = va.y;
            sA[c4 + 2][row] = va.z;
            sA[c4 + 3][row] = va.w;
            float4 vb = *(const float4*)(W + (size_t)(bn + row) * K + k0 + c4);
            sB[c4 + 0][row] = vb.x;
            sB[c4 + 1][row] = vb.y;
            sB[c4 + 2][row] = vb.z;
            sB[c4 + 3][row] = vb.w;
        }
        __syncthreads();

        #pragma unroll
        for (int k = 0; k < 32; k++) {
            float4 a4 = *(const float4*)&sA[k][ty * 4];
            float4 b4 = *(const float4*)&sB[k][tx * 4];
            float av[4] = {a4.x, a4.y, a4.z, a4.w};
            float bv[4] = {b4.x, b4.y, b4.z, b4.w};
            #pragma unroll
            for (int i = 0; i < 4; i++)
                #pragma unroll
                for (int j = 0; j < 4; j++)
                    acc[i][j] += av[i] * bv[j];
        }
        __syncthreads();
    }

    float4 bsv = *(const float4*)(bias + bn + tx * 4);
    #pragma unroll
    for (int i = 0; i < 4; i++) {
        float4 r;
        r.x = acc[i][0] + bsv.x;
        r.y = acc[i][1] + bsv.y;
        r.z = acc[i][2] + bsv.z;
        r.w = acc[i][3] + bsv.w;
        *(float4*)(C + (size_t)(bm + ty * 4 + i) * N + bn + tx * 4) = r;
    }
}

// ---------------------------------------------------------------------------
// Flash attention, fp32, online softmax.
// Grid: (S/64, H, B). Block: 256 threads (16x16), 64 q-rows per block,
// loops over S/64 key tiles of 64. D = 64.
// smem: sQt [d][r] (scaled by 1/8), sKt [d][c], sV [c][d], sPt [c][r];
// all [64][68] → 69632 B dynamic smem.
// ---------------------------------------------------------------------------
#define FPAD 68
#define FLASH_SMEM (4 * 64 * FPAD * 4)

__global__ __launch_bounds__(256) void flash_attn(
    const float* __restrict__ Q, const float* __restrict__ K,
    const float* __restrict__ V, float* __restrict__ ctx, int S)
{
    extern __shared__ float sm[];
    float* sQt = sm;                  // [64][68]  (d, r)
    float* sKt = sm + 64 * FPAD;      // [64][68]  (d, c)
    float* sV  = sm + 2 * 64 * FPAD;  // [64][68]  (c, d)
    float* sPt = sm + 3 * 64 * FPAD;  // [64][68]  (c, r)

    const int tid = threadIdx.x;
    const int tx  = tid & 15;
    const int ty  = tid >> 4;
    const int s0  = blockIdx.x * 64;
    const int h   = blockIdx.y;
    const int b   = blockIdx.z;
    const size_t base = ((size_t)b * S) * EMBED + (size_t)h * HDIM;

    // Load 64x64 Q tile, transposed + pre-scaled by 1/sqrt(64) = 0.125.
    #pragma unroll
    for (int i = 0; i < 4; i++) {
        int idx = tid + i * 256;          // 0..1023 float4 slots
        int row = idx >> 4;               // 0..63
        int d4  = (idx & 15) << 2;        // 0..60
        float4 v = *(const float4*)(Q + base + (size_t)(s0 + row) * EMBED + d4);
        sQt[(d4 + 0) * FPAD + row] = v.x * 0.125f;
        sQt[(d4 + 1) * FPAD + row] = v.y * 0.125f;
        sQt[(d4 + 2) * FPAD + row] = v.z * 0.125f;
        sQt[(d4 + 3) * FPAD + row] = v.w * 0.125f;
    }

    float o[4][4] = {};
    float mrow[4] = {-1e30f, -1e30f, -1e30f, -1e30f};
    float lrow[4] = {0.f, 0.f, 0.f, 0.f};

    const int nkt = S >> 6;
    for (int kt = 0; kt < nkt; kt++) {
        const int c0 = kt * 64;
        __syncthreads();   // prior iter done reading sKt/sV/sPt; Q ready on iter 0

        // Load K tile (transposed) and V tile (natural).
        #pragma unroll
        for (int i = 0; i < 4; i++) {
            int idx = tid + i * 256;
            int row = idx >> 4;
            int d4  = (idx & 15) << 2;
            float4 vk = *(const float4*)(K + base + (size_t)(c0 + row) * EMBED + d4);
            sKt[(d4 + 0) * FPAD + row] = vk.x;
            sKt[(d4 + 1) * FPAD + row] = vk.y;
            sKt[(d4 + 2) * FPAD + row] = vk.z;
            sKt[(d4 + 3) * FPAD + row] = vk.w;
            float4 vv = *(const float4*)(V + base + (size_t)(c0 + row) * EMBED + d4);
            *(float4*)&sV[row * FPAD + d4] = vv;
        }
        __syncthreads();

        // S tile: s[i][j] = sum_d Qt[d][ty*4+i] * Kt[d][tx*4+j]
        float s[4][4] = {};
        #pragma unroll
        for (int d = 0; d < 64; d++) {
            float4 a4 = *(const float4*)&sQt[d * FPAD + ty * 4];
            float4 b4 = *(const float4*)&sKt[d * FPAD + tx * 4];
            float av[4] = {a4.x, a4.y, a4.z, a4.w};
            float bv[4] = {b4.x, b4.y, b4.z, b4.w};
            #pragma unroll
            for (int i = 0; i < 4; i++)
                #pragma unroll
                for (int j = 0; j < 4; j++)
                    s[i][j] += av[i] * bv[j];
        }

        // Online softmax per row; row group = 16 lanes sharing ty.
        #pragma unroll
        for (int i = 0; i < 4; i++) {
            float mx = fmaxf(fmaxf(s[i][0], s[i][1]), fmaxf(s[i][2], s[i][3]));
            #pragma unroll
            for (int off = 8; off > 0; off >>= 1)
                mx = fmaxf(mx, __shfl_xor_sync(0xffffffffu, mx, off, 16));
            float mnew  = fmaxf(mrow[i], mx);
            float alpha = __expf(mrow[i] - mnew);
            float ps = 0.f;
            #pragma unroll
            for (int j = 0; j < 4; j++) {
                s[i][j] = __expf(s[i][j] - mnew);
                ps += s[i][j];
            }
            #pragma unroll
            for (int off = 8; off > 0; off >>= 1)
                ps += __shfl_xor_sync(0xffffffffu, ps, off, 16);
            lrow[i] = lrow[i] * alpha + ps;
            mrow[i] = mnew;
            #pragma unroll
            for (int j = 0; j < 4; j++) {
                o[i][0 + j] *= 1.f;  // placeholder to keep unroller simple
            }
            o[i][0] *= alpha; o[i][1] *= alpha; o[i][2] *= alpha; o[i][3] *= alpha;
        }

        // Write P transposed: sPt[c][r].
        #pragma unroll
        for (int j = 0; j < 4; j++) {
            float4 p4;
            p4.x = s[0][j]; p4.y = s[1][j]; p4.z = s[2][j]; p4.w = s[3][j];
            *(float4*)&sPt[(tx * 4 + j) * FPAD + ty * 4] = p4;
        }
        __syncthreads();

        // O += P @ V: o[i][j] += sum_c Pt[c][ty*4+i] * V[c][tx*4+j]
        #pragma unroll
        for (int c = 0; c < 64; c++) {
            float4 p4 = *(const float4*)&sPt[c * FPAD + ty * 4];
            float4 v4 = *(const float4*)&sV[c * FPAD + tx * 4];
            float pv[4] = {p4.x, p4.y, p4.z, p4.w};
            float vv[4] = {v4.x, v4.y, v4.z, v4.w};
            #pragma unroll
            for (int i = 0; i < 4; i++)
                #pragma unroll
                for (int j = 0; j < 4; j++)
                    o[i][j] += pv[i] * vv[j];
        }
    }

    // Epilogue: ctx[b, s0+r, h*64+d] = o / l
    #pragma unroll
    for (int i = 0; i < 4; i++) {
        float inv = 1.f / lrow[i];
        float4 r;
        r.x = o[i][0] * inv;
        r.y = o[i][1] * inv;
        r.z = o[i][2] * inv;
        r.w = o[i][3] * inv;
        *(float4*)(ctx + base + (size_t)(s0 + ty * 4 + i) * EMBED + tx * 4) = r;
    }
}

// ---------------------------------------------------------------------------
extern "C" void kernel_launch(void* const* d_in, const int* in_sizes, int n_in,
                              void* d_out, int out_size)
{
    const float* query = (const float*)d_in[0];
    const float* key   = (const float*)d_in[1];
    const float* value = (const float*)d_in[2];
    const float* Wq    = (const float*)d_in[3];
    const float* bq    = (const float*)d_in[4];
    const float* Wk    = (const float*)d_in[5];
    const float* bk    = (const float*)d_in[6];
    const float* Wv    = (const float*)d_in[7];
    const float* bv    = (const float*)d_in[8];
    const float* Wo    = (const float*)d_in[9];
    const float* bo    = (const float*)d_in[10];
    float* out = (float*)d_out;

    const int M = in_sizes[0] / EMBED;   // 4096 = B*S
    const int B = 2;
    const int S = M / B;                 // 2048

    float *q, *k, *v, *ctx;
    cudaGetSymbolAddress((void**)&q,   g_q);
    cudaGetSymbolAddress((void**)&k,   g_k);
    cudaGetSymbolAddress((void**)&v,   g_v);
    cudaGetSymbolAddress((void**)&ctx, g_ctx);

    cudaFuncSetAttribute(flash_attn,
                         cudaFuncAttributeMaxDynamicSharedMemorySize, FLASH_SMEM);

    dim3 ggrid(M / 64, EMBED / 64);
    gemm_nt_bias<<<ggrid, 256>>>(query, Wq, bq, q, M, EMBED, EMBED);
    gemm_nt_bias<<<ggrid, 256>>>(key,   Wk, bk, k, M, EMBED, EMBED);
    gemm_nt_bias<<<ggrid, 256>>>(value, Wv, bv, v, M, EMBED, EMBED);

    dim3 agrid(S / 64, NHEADS, B);
    flash_attn<<<agrid, 256, FLASH_SMEM>>>(q, k, v, ctx, S);

    gemm_nt_bias<<<ggrid, 256>>>(ctx, Wo, bo, out, M, EMBED, EMBED);
}

// round 3
// speedup vs baseline: 1.5291x; 1.5291x over previous
#include <cuda_runtime.h>
#include <cstdint>
#include <math.h>

#define EMBED   1024
#define NHEADS  16
#define MAXROWS 4096   // B*S

// Scratch (no cudaMalloc allowed) — [B,S,E] layout, head h at col h*64.
__device__ float g_q  [MAXROWS * EMBED];
__device__ float g_k  [MAXROWS * EMBED];
__device__ float g_v  [MAXROWS * EMBED];
__device__ float g_ctx[MAXROWS * EMBED];

// ============================ helpers ======================================
__device__ __forceinline__ uint32_t f2tf32(float x) {
    uint32_t u;
    asm("cvt.rna.tf32.f32 %0, %1;" : "=r"(u) : "f"(x));
    return u;
}

// m16n8k8 tf32 MMA, row.col, fp32 accumulate in place.
__device__ __forceinline__ void mma8(float* d, const uint32_t* a, const uint32_t* b) {
    asm volatile(
        "mma.sync.aligned.m16n8k8.row.col.f32.tf32.tf32.f32 "
        "{%0,%1,%2,%3},{%4,%5,%6,%7},{%8,%9},{%0,%1,%2,%3};"
        : "+f"(d[0]), "+f"(d[1]), "+f"(d[2]), "+f"(d[3])
        : "r"(a[0]), "r"(a[1]), "r"(a[2]), "r"(a[3]), "r"(b[0]), "r"(b[1]));
}

// ===========================================================================
// tf32 tensor-core NT GEMM: C[m,n] = sum_k A[m,k]*W[n,k] + bias[n]
// CTA tile 128x128, K-chunk 32, 256 threads = 8 warps in 2(m) x 4(n),
// warp tile 64x32 -> 4x4 m16n8k8 fragments per k8-step.
// smem: rows of 32 floats (128B), float4-column XOR swizzle (c4 ^ (row&7)):
// conflict-free STS.128 on fill and conflict-free LDS.32 fragment gathers.
// Double-buffered; chunk c+1 LDG overlapped with MMA of chunk c.
// All values rounded to tf32 with cvt.rna on the smem-store path.
// blockIdx.z selects one of 3 fused problems.
// ===========================================================================
#define G_SMEM_BYTES 65536   // 2 stages x (A 16KB + W 16KB)

__global__ __launch_bounds__(256) void gemm3_mma(
    const float* __restrict__ A0, const float* __restrict__ A1, const float* __restrict__ A2,
    const float* __restrict__ W0, const float* __restrict__ W1, const float* __restrict__ W2,
    const float* __restrict__ b0, const float* __restrict__ b1, const float* __restrict__ b2,
    float* __restrict__ C0, float* __restrict__ C1, float* __restrict__ C2,
    int M, int N, int K)
{
    extern __shared__ float smf[];
    uint32_t* smu = (uint32_t*)smf;

    const int tid  = threadIdx.x;
    const int lane = tid & 31;
    const int wid  = tid >> 5;
    const int g    = lane >> 2;     // 0..7
    const int tig  = lane & 3;      // 0..3
    const int wm   = wid & 1;       // 0..1
    const int wn   = wid >> 1;      // 0..3
    const int bm   = blockIdx.x * 128;
    const int bn   = blockIdx.y * 128;
    const int z    = blockIdx.z;

    const float* A    = (z == 0) ? A0 : (z == 1) ? A1 : A2;
    const float* W    = (z == 0) ? W0 : (z == 1) ? W1 : W2;
    const float* bias = (z == 0) ? b0 : (z == 1) ? b1 : b2;
    float*       C    = (z == 0) ? C0 : (z == 1) ? C1 : C2;

    const int lrow = tid >> 3;      // 0..31 (row within 32-row pass)
    const int lc4  = tid & 7;       // float4 column 0..7

    float acc[4][4][4];
    #pragma unroll
    for (int mt = 0; mt < 4; mt++)
        #pragma unroll
        for (int nt = 0; nt < 4; nt++)
            #pragma unroll
            for (int r = 0; r < 4; r++) acc[mt][nt][r] = 0.f;

    float4 va[4], vw[4];

    // Prologue: load + convert + store chunk 0 into buffer 0.
    #pragma unroll
    for (int p = 0; p < 4; p++) {
        va[p] = *(const float4*)(A + (size_t)(bm + lrow + p * 32) * K + lc4 * 4);
        vw[p] = *(const float4*)(W + (size_t)(bn + lrow + p * 32) * K + lc4 * 4);
    }
    #pragma unroll
    for (int p = 0; p < 4; p++) {
        int r   = lrow + p * 32;
        int idx = r * 32 + ((lc4 ^ (r & 7)) << 2);
        *(uint4*)(smu + idx) =
            make_uint4(f2tf32(va[p].x), f2tf32(va[p].y), f2tf32(va[p].z), f2tf32(va[p].w));
        *(uint4*)(smu + 4096 + idx) =
            make_uint4(f2tf32(vw[p].x), f2tf32(vw[p].y), f2tf32(vw[p].z), f2tf32(vw[p].w));
    }
    __syncthreads();

    const int NCH = K >> 5;   // 32
    for (int c = 0; c < NCH; c++) {
        const int s = c & 1;
        if (c + 1 < NCH) {
            const int k0 = (c + 1) * 32;
            #pragma unroll
            for (int p = 0; p < 4; p++) {
                va[p] = *(const float4*)(A + (size_t)(bm + lrow + p * 32) * K + k0 + lc4 * 4);
                vw[p] = *(const float4*)(W + (size_t)(bn + lrow + p * 32) * K + k0 + lc4 * 4);
            }
        }
        const uint32_t* sA = smu + s * 8192;
        const uint32_t* sW = sA + 4096;

        #pragma unroll
        for (int kk = 0; kk < 4; kk++) {
            uint32_t af[4][4], bf[4][2];
            #pragma unroll
            for (int mt = 0; mt < 4; mt++) {
                int r0 = wm * 64 + mt * 16 + g;
                int r1 = r0 + 8;
                af[mt][0] = sA[r0 * 32 + (((2 * kk)     ^ (r0 & 7)) << 2) + tig];
                af[mt][1] = sA[r1 * 32 + (((2 * kk)     ^ (r1 & 7)) << 2) + tig];
                af[mt][2] = sA[r0 * 32 + (((2 * kk + 1) ^ (r0 & 7)) << 2) + tig];
                af[mt][3] = sA[r1 * 32 + (((2 * kk + 1) ^ (r1 & 7)) << 2) + tig];
            }
            #pragma unroll
            for (int nt = 0; nt < 4; nt++) {
                int rn = wn * 32 + nt * 8 + g;
                bf[nt][0] = sW[rn * 32 + (((2 * kk)     ^ (rn & 7)) << 2) + tig];
                bf[nt][1] = sW[rn * 32 + (((2 * kk + 1) ^ (rn & 7)) << 2) + tig];
            }
            #pragma unroll
            for (int mt = 0; mt < 4; mt++)
                #pragma unroll
                for (int nt = 0; nt < 4; nt++)
                    mma8(acc[mt][nt], af[mt], bf[nt]);
        }

        if (c + 1 < NCH) {
            uint32_t* dA = smu + (s ^ 1) * 8192;
            #pragma unroll
            for (int p = 0; p < 4; p++) {
                int r   = lrow + p * 32;
                int idx = r * 32 + ((lc4 ^ (r & 7)) << 2);
                *(uint4*)(dA + idx) =
                    make_uint4(f2tf32(va[p].x), f2tf32(va[p].y), f2tf32(va[p].z), f2tf32(va[p].w));
                *(uint4*)(dA + 4096 + idx) =
                    make_uint4(f2tf32(vw[p].x), f2tf32(vw[p].y), f2tf32(vw[p].z), f2tf32(vw[p].w));
            }
        }
        __syncthreads();
    }

    // Epilogue: c-frag rows {g, g+8}, cols {2tig, 2tig+1}.
    #pragma unroll
    for (int nt = 0; nt < 4; nt++) {
        int col = bn + wn * 32 + nt * 8 + tig * 2;
        float2 bv = *(const float2*)(bias + col);
        #pragma unroll
        for (int mt = 0; mt < 4; mt++) {
            int r0 = bm + wm * 64 + mt * 16 + g;
            float2 v0 = make_float2(acc[mt][nt][0] + bv.x, acc[mt][nt][1] + bv.y);
            float2 v1 = make_float2(acc[mt][nt][2] + bv.x, acc[mt][nt][3] + bv.y);
            *(float2*)(C + (size_t)r0 * N + col)       = v0;
            *(float2*)(C + (size_t)(r0 + 8) * N + col) = v1;
        }
    }
}

// ===========================================================================
// Flash attention v2: 128 q-rows x 64 k-cols per iter, 256 threads,
// 8x4 per-thread tile. P stored row-major (conflict-free STS; PV reads
// P as broadcast float2 pairs). D=64.
// ===========================================================================
#define QP 132
#define KP 68
#define OFF_QT 0                             // [64][132] (d, r)
#define OFF_KT 8448                          // [64][68]  (d, c)
#define OFF_V  12800                         // [64][68]  (c, d)
#define OFF_P  17152                         // [128][68] (r, c)
#define FLASH_SMEM2 ((17152 + 128 * 68) * 4) // 103424 B

__global__ __launch_bounds__(256, 2) void flash_attn2(
    const float* __restrict__ Q, const float* __restrict__ K,
    const float* __restrict__ V, float* __restrict__ ctx, int S)
{
    extern __shared__ float sm[];
    float* sQt = sm + OFF_QT;
    float* sKt = sm + OFF_KT;
    float* sV  = sm + OFF_V;
    float* sP  = sm + OFF_P;

    const int tid = threadIdx.x;
    const int tx  = tid & 15;
    const int ty  = tid >> 4;
    const int s0  = blockIdx.x * 128;
    const int h   = blockIdx.y;
    const int b   = blockIdx.z;
    const size_t base = ((size_t)b * S) * EMBED + (size_t)h * 64;

    #pragma unroll
    for (int i = 0; i < 8; i++) {
        int idx = tid + i * 256;
        int row = idx >> 4;
        int d4  = (idx & 15) << 2;
        float4 v = *(const float4*)(Q + base + (size_t)(s0 + row) * EMBED + d4);
        sQt[(d4 + 0) * QP + row] = v.x * 0.125f;
        sQt[(d4 + 1) * QP + row] = v.y * 0.125f;
        sQt[(d4 + 2) * QP + row] = v.z * 0.125f;
        sQt[(d4 + 3) * QP + row] = v.w * 0.125f;
    }

    float o[8][4] = {};
    float m[8], l[8];
    #pragma unroll
    for (int i = 0; i < 8; i++) { m[i] = -1e30f; l[i] = 0.f; }

    const int nkt = S >> 6;
    for (int kt = 0; kt < nkt; kt++) {
        const int c0 = kt * 64;
        __syncthreads();

        #pragma unroll
        for (int i = 0; i < 4; i++) {
            int idx = tid + i * 256;
            int row = idx >> 4;
            int d4  = (idx & 15) << 2;
            float4 vk = *(const float4*)(K + base + (size_t)(c0 + row) * EMBED + d4);
            sKt[(d4 + 0) * KP + row] = vk.x;
            sKt[(d4 + 1) * KP + row] = vk.y;
            sKt[(d4 + 2) * KP + row] = vk.z;
            sKt[(d4 + 3) * KP + row] = vk.w;
            float4 vv = *(const float4*)(V + base + (size_t)(c0 + row) * EMBED + d4);
            *(float4*)&sV[row * KP + d4] = vv;
        }
        __syncthreads();

        float s[8][4] = {};
        #pragma unroll
        for (int d = 0; d < 64; d++) {
            float4 a0 = *(const float4*)&sQt[d * QP + ty * 8];
            float4 a1 = *(const float4*)&sQt[d * QP + ty * 8 + 4];
            float4 b4 = *(const float4*)&sKt[d * KP + tx * 4];
            float av[8] = {a0.x, a0.y, a0.z, a0.w, a1.x, a1.y, a1.z, a1.w};
            float bv[4] = {b4.x, b4.y, b4.z, b4.w};
            #pragma unroll
            for (int i = 0; i < 8; i++)
                #pragma unroll
                for (int j = 0; j < 4; j++)
                    s[i][j] += av[i] * bv[j];
        }

        #pragma unroll
        for (int i = 0; i < 8; i++) {
            float mx = fmaxf(fmaxf(s[i][0], s[i][1]), fmaxf(s[i][2], s[i][3]));
            #pragma unroll
            for (int off = 8; off > 0; off >>= 1)
                mx = fmaxf(mx, __shfl_xor_sync(0xffffffffu, mx, off, 16));
            float mnew  = fmaxf(m[i], mx);
            float alpha = __expf(m[i] - mnew);
            float ps = 0.f;
            #pragma unroll
            for (int j = 0; j < 4; j++) { s[i][j] = __expf(s[i][j] - mnew); ps += s[i][j]; }
            #pragma unroll
            for (int off = 8; off > 0; off >>= 1)
                ps += __shfl_xor_sync(0xffffffffu, ps, off, 16);
            l[i] = l[i] * alpha + ps;
            m[i] = mnew;
            o[i][0] *= alpha; o[i][1] *= alpha; o[i][2] *= alpha; o[i][3] *= alpha;
        }

        #pragma unroll
        for (int i = 0; i < 8; i++)
            *(float4*)&sP[(ty * 8 + i) * KP + tx * 4] =
                make_float4(s[i][0], s[i][1], s[i][2], s[i][3]);
        __syncthreads();

        #pragma unroll 4
        for (int c2 = 0; c2 < 64; c2 += 2) {
            float4 va = *(const float4*)&sV[c2 * KP + tx * 4];
            float4 vb = *(const float4*)&sV[(c2 + 1) * KP + tx * 4];
            #pragma unroll
            for (int i = 0; i < 8; i++) {
                float2 p = *(const float2*)&sP[(ty * 8 + i) * KP + c2];
                o[i][0] += p.x * va.x + p.y * vb.x;
                o[i][1] += p.x * va.y + p.y * vb.y;
                o[i][2] += p.x * va.z + p.y * vb.z;
                o[i][3] += p.x * va.w + p.y * vb.w;
            }
        }
    }

    #pragma unroll
    for (int i = 0; i < 8; i++) {
        float inv = 1.f / l[i];
        *(float4*)(ctx + base + (size_t)(s0 + ty * 8 + i) * EMBED + tx * 4) =
            make_float4(o[i][0] * inv, o[i][1] * inv, o[i][2] * inv, o[i][3] * inv);
    }
}

// ===========================================================================
extern "C" void kernel_launch(void* const* d_in, const int* in_sizes, int n_in,
                              void* d_out, int out_size)
{
    const float* query = (const float*)d_in[0];
    const float* key   = (const float*)d_in[1];
    const float* value = (const float*)d_in[2];
    const float* Wq    = (const float*)d_in[3];
    const float* bq    = (const float*)d_in[4];
    const float* Wk    = (const float*)d_in[5];
    const float* bk    = (const float*)d_in[6];
    const float* Wv    = (const float*)d_in[7];
    const float* bv    = (const float*)d_in[8];
    const float* Wo    = (const float*)d_in[9];
    const float* bo    = (const float*)d_in[10];
    float* out = (float*)d_out;

    const int M = in_sizes[0] / EMBED;   // 4096
    const int B = 2;
    const int S = M / B;                 // 2048

    float *q, *k, *v, *ctx;
    cudaGetSymbolAddress((void**)&q,   g_q);
    cudaGetSymbolAddress((void**)&k,   g_k);
    cudaGetSymbolAddress((void**)&v,   g_v);
    cudaGetSymbolAddress((void**)&ctx, g_ctx);

    cudaFuncSetAttribute(gemm3_mma,
                         cudaFuncAttributeMaxDynamicSharedMemorySize, G_SMEM_BYTES);
    cudaFuncSetAttribute(flash_attn2,
                         cudaFuncAttributeMaxDynamicSharedMemorySize, FLASH_SMEM2);

    dim3 g3(M / 128, EMBED / 128, 3);
    gemm3_mma<<<g3, 256, G_SMEM_BYTES>>>(query, key, value,
                                         Wq, Wk, Wv, bq, bk, bv,
                                         q, k, v, M, EMBED, EMBED);

    dim3 agrid(S / 128, NHEADS, B);
    flash_attn2<<<agrid, 256, FLASH_SMEM2>>>(q, k, v, ctx, S);

    dim3 g1(M / 128, EMBED / 128, 1);
    gemm3_mma<<<g1, 256, G_SMEM_BYTES>>>(ctx, ctx, ctx,
                                         Wo, Wo, Wo, bo, bo, bo,
                                         out, out, out, M, EMBED, EMBED);
}

// round 4
// speedup vs baseline: 3.4656x; 2.2665x over previous
#include <cuda_runtime.h>
#include <cuda_fp16.h>
#include <cstdint>
#include <math.h>

#define EMBED   1024
#define NHEADS  16
#define MAXROWS 4096   // B*S

// Scratch (no cudaMalloc allowed) — [B,S,E] layout, head h at col h*64.
__device__ float g_q  [MAXROWS * EMBED];
__device__ float g_k  [MAXROWS * EMBED];
__device__ float g_v  [MAXROWS * EMBED];
__device__ float g_ctx[MAXROWS * EMBED];

// ============================ helpers ======================================
__device__ __forceinline__ uint32_t f2tf32(float x) {
    uint32_t u;
    asm("cvt.rna.tf32.f32 %0, %1;" : "=r"(u) : "f"(x));
    return u;
}
__device__ __forceinline__ uint32_t smem_u32(const void* p) {
    uint32_t a;
    asm("{ .reg .u64 t; cvta.to.shared.u64 t, %1; cvt.u32.u64 %0, t; }"
        : "=r"(a) : "l"(p));
    return a;
}
__device__ __forceinline__ uint32_t packh2(float lo, float hi) {
    __half2 h = __floats2half2_rn(lo, hi);   // .x = lo (low half)
    return *(uint32_t*)&h;
}
// Fast exp2 on the FMA/ALU pipes (x <= 0 expected; clamped). |err| ~ 2e-6.
__device__ __forceinline__ float exp2p(float x) {
    x = fmaxf(x, -100.f);
    float r = rintf(x);
    float f = x - r;                          // [-0.5, 0.5]
    float p = 1.3333558e-3f;
    p = fmaf(p, f, 9.6181292e-3f);
    p = fmaf(p, f, 5.5504109e-2f);
    p = fmaf(p, f, 2.4022651e-1f);
    p = fmaf(p, f, 6.9314718e-1f);
    p = fmaf(p, f, 1.0f);
    int i = (int)r;
    return __int_as_float(__float_as_int(p) + (i << 23));
}

// m16n8k8 tf32 MMA (GEMM), fp32 accumulate in place.
__device__ __forceinline__ void mma8(float* d, const uint32_t* a, const uint32_t* b) {
    asm volatile(
        "mma.sync.aligned.m16n8k8.row.col.f32.tf32.tf32.f32 "
        "{%0,%1,%2,%3},{%4,%5,%6,%7},{%8,%9},{%0,%1,%2,%3};"
        : "+f"(d[0]), "+f"(d[1]), "+f"(d[2]), "+f"(d[3])
        : "r"(a[0]), "r"(a[1]), "r"(a[2]), "r"(a[3]), "r"(b[0]), "r"(b[1]));
}
// m16n8k16 fp16 MMA (attention), fp32 accumulate in place.
__device__ __forceinline__ void mma16(float* d, const uint32_t* a, uint32_t b0, uint32_t b1) {
    asm volatile(
        "mma.sync.aligned.m16n8k16.row.col.f32.f16.f16.f32 "
        "{%0,%1,%2,%3},{%4,%5,%6,%7},{%8,%9},{%0,%1,%2,%3};"
        : "+f"(d[0]), "+f"(d[1]), "+f"(d[2]), "+f"(d[3])
        : "r"(a[0]), "r"(a[1]), "r"(a[2]), "r"(a[3]), "r"(b0), "r"(b1));
}
__device__ __forceinline__ void ldsm_x2(uint32_t& r0, uint32_t& r1, uint32_t addr) {
    asm volatile("ldmatrix.sync.aligned.m8n8.x2.shared.b16 {%0,%1}, [%2];"
                 : "=r"(r0), "=r"(r1) : "r"(addr));
}
__device__ __forceinline__ void ldsm_x2t(uint32_t& r0, uint32_t& r1, uint32_t addr) {
    asm volatile("ldmatrix.sync.aligned.m8n8.x2.trans.shared.b16 {%0,%1}, [%2];"
                 : "=r"(r0), "=r"(r1) : "r"(addr));
}
__device__ __forceinline__ void ldsm_x4(uint32_t* r, uint32_t addr) {
    asm volatile("ldmatrix.sync.aligned.m8n8.x4.shared.b16 {%0,%1,%2,%3}, [%4];"
                 : "=r"(r[0]), "=r"(r[1]), "=r"(r[2]), "=r"(r[3]) : "r"(addr));
}

// ===========================================================================
// tf32 tensor-core NT GEMM (unchanged from R3, validated):
// C[m,n] = sum_k A[m,k]*W[n,k] + bias[n]. 128x128 tile, K-chunk 32, 8 warps.
// ===========================================================================
#define G_SMEM_BYTES 65536

__global__ __launch_bounds__(256) void gemm3_mma(
    const float* __restrict__ A0, const float* __restrict__ A1, const float* __restrict__ A2,
    const float* __restrict__ W0, const float* __restrict__ W1, const float* __restrict__ W2,
    const float* __restrict__ b0, const float* __restrict__ b1, const float* __restrict__ b2,
    float* __restrict__ C0, float* __restrict__ C1, float* __restrict__ C2,
    int M, int N, int K)
{
    extern __shared__ float smf[];
    uint32_t* smu = (uint32_t*)smf;

    const int tid  = threadIdx.x;
    const int lane = tid & 31;
    const int wid  = tid >> 5;
    const int g    = lane >> 2;
    const int tig  = lane & 3;
    const int wm   = wid & 1;
    const int wn   = wid >> 1;
    const int bm   = blockIdx.x * 128;
    const int bn   = blockIdx.y * 128;
    const int z    = blockIdx.z;

    const float* A    = (z == 0) ? A0 : (z == 1) ? A1 : A2;
    const float* W    = (z == 0) ? W0 : (z == 1) ? W1 : W2;
    const float* bias = (z == 0) ? b0 : (z == 1) ? b1 : b2;
    float*       C    = (z == 0) ? C0 : (z == 1) ? C1 : C2;

    const int lrow = tid >> 3;
    const int lc4  = tid & 7;

    float acc[4][4][4];
    #pragma unroll
    for (int mt = 0; mt < 4; mt++)
        #pragma unroll
        for (int nt = 0; nt < 4; nt++)
            #pragma unroll
            for (int r = 0; r < 4; r++) acc[mt][nt][r] = 0.f;

    float4 va[4], vw[4];

    #pragma unroll
    for (int p = 0; p < 4; p++) {
        va[p] = *(const float4*)(A + (size_t)(bm + lrow + p * 32) * K + lc4 * 4);
        vw[p] = *(const float4*)(W + (size_t)(bn + lrow + p * 32) * K + lc4 * 4);
    }
    #pragma unroll
    for (int p = 0; p < 4; p++) {
        int r   = lrow + p * 32;
        int idx = r * 32 + ((lc4 ^ (r & 7)) << 2);
        *(uint4*)(smu + idx) =
            make_uint4(f2tf32(va[p].x), f2tf32(va[p].y), f2tf32(va[p].z), f2tf32(va[p].w));
        *(uint4*)(smu + 4096 + idx) =
            make_uint4(f2tf32(vw[p].x), f2tf32(vw[p].y), f2tf32(vw[p].z), f2tf32(vw[p].w));
    }
    __syncthreads();

    const int NCH = K >> 5;
    for (int c = 0; c < NCH; c++) {
        const int s = c & 1;
        if (c + 1 < NCH) {
            const int k0 = (c + 1) * 32;
            #pragma unroll
            for (int p = 0; p < 4; p++) {
                va[p] = *(const float4*)(A + (size_t)(bm + lrow + p * 32) * K + k0 + lc4 * 4);
                vw[p] = *(const float4*)(W + (size_t)(bn + lrow + p * 32) * K + k0 + lc4 * 4);
            }
        }
        const uint32_t* sA = smu + s * 8192;
        const uint32_t* sW = sA + 4096;

        #pragma unroll
        for (int kk = 0; kk < 4; kk++) {
            uint32_t af[4][4], bf[4][2];
            #pragma unroll
            for (int mt = 0; mt < 4; mt++) {
                int r0 = wm * 64 + mt * 16 + g;
                int r1 = r0 + 8;
                af[mt][0] = sA[r0 * 32 + (((2 * kk)     ^ (r0 & 7)) << 2) + tig];
                af[mt][1] = sA[r1 * 32 + (((2 * kk)     ^ (r1 & 7)) << 2) + tig];
                af[mt][2] = sA[r0 * 32 + (((2 * kk + 1) ^ (r0 & 7)) << 2) + tig];
                af[mt][3] = sA[r1 * 32 + (((2 * kk + 1) ^ (r1 & 7)) << 2) + tig];
            }
            #pragma unroll
            for (int nt = 0; nt < 4; nt++) {
                int rn = wn * 32 + nt * 8 + g;
                bf[nt][0] = sW[rn * 32 + (((2 * kk)     ^ (rn & 7)) << 2) + tig];
                bf[nt][1] = sW[rn * 32 + (((2 * kk + 1) ^ (rn & 7)) << 2) + tig];
            }
            #pragma unroll
            for (int mt = 0; mt < 4; mt++)
                #pragma unroll
                for (int nt = 0; nt < 4; nt++)
                    mma8(acc[mt][nt], af[mt], bf[nt]);
        }

        if (c + 1 < NCH) {
            uint32_t* dA = smu + (s ^ 1) * 8192;
            #pragma unroll
            for (int p = 0; p < 4; p++) {
                int r   = lrow + p * 32;
                int idx = r * 32 + ((lc4 ^ (r & 7)) << 2);
                *(uint4*)(dA + idx) =
                    make_uint4(f2tf32(va[p].x), f2tf32(va[p].y), f2tf32(va[p].z), f2tf32(va[p].w));
                *(uint4*)(dA + 4096 + idx) =
                    make_uint4(f2tf32(vw[p].x), f2tf32(vw[p].y), f2tf32(vw[p].z), f2tf32(vw[p].w));
            }
        }
        __syncthreads();
    }

    #pragma unroll
    for (int nt = 0; nt < 4; nt++) {
        int col = bn + wn * 32 + nt * 8 + tig * 2;
        float2 bv = *(const float2*)(bias + col);
        #pragma unroll
        for (int mt = 0; mt < 4; mt++) {
            int r0 = bm + wm * 64 + mt * 16 + g;
            *(float2*)(C + (size_t)r0 * N + col) =
                make_float2(acc[mt][nt][0] + bv.x, acc[mt][nt][1] + bv.y);
            *(float2*)(C + (size_t)(r0 + 8) * N + col) =
                make_float2(acc[mt][nt][2] + bv.x, acc[mt][nt][3] + bv.y);
        }
    }
}

// ===========================================================================
// fp16 tensor-core flash attention (FA2-style).
// CTA: 128 q-rows x full D=64, 8 warps x 16 q-rows. Key tiles of 64, double-
// buffered fp16 K/V in smem. S computed in log2-units (Q pre-scaled by
// 0.125*log2e); softmax via FFMA exp2 poly; P stays in registers as the
// A-fragment of the PV mma (C-frag layout == A-frag layout trick).
// ===========================================================================
#define HPAD 72                     // half-elem row stride (144B: LDSM conflict-free)
#define OFF_Q  0                    // [128][72] halves
#define OFF_K0 (128 * HPAD)         // [64][72]
#define OFF_V0 (OFF_K0 + 64 * HPAD)
#define OFF_K1 (OFF_V0 + 64 * HPAD)
#define OFF_V1 (OFF_K1 + 64 * HPAD)
#define FLASH_SMEM ((OFF_V1 + 64 * HPAD) * 2)   // 55296 B
#define QSCALE 0.18033688011112042f             // (1/8) * log2(e)

__global__ __launch_bounds__(256) void flash_tc(
    const float* __restrict__ Q, const float* __restrict__ K,
    const float* __restrict__ V, float* __restrict__ ctx, int S)
{
    extern __shared__ __half smh[];
    const uint32_t sb = smem_u32(smh);

    const int tid  = threadIdx.x;
    const int lane = tid & 31;
    const int warp = tid >> 5;
    const int g    = lane >> 2;
    const int tig  = lane & 3;
    const int s0   = blockIdx.x * 128;
    const int h    = blockIdx.y;
    const int b    = blockIdx.z;
    const size_t base = ((size_t)b * S) * EMBED + (size_t)h * 64;

    // ---- stage Q (scaled) into smem fp16 ----
    #pragma unroll
    for (int i = 0; i < 8; i++) {
        int slot = tid + i * 256;           // 0..2047 float4 slots
        int row  = slot >> 4;               // 0..127
        int c4   = (slot & 15) << 2;
        float4 v = *(const float4*)(Q + base + (size_t)(s0 + row) * EMBED + c4);
        uint2 st;
        st.x = packh2(v.x * QSCALE, v.y * QSCALE);
        st.y = packh2(v.z * QSCALE, v.w * QSCALE);
        *(uint2*)(smh + OFF_Q + row * HPAD + c4) = st;
    }
    // ---- stage K/V tile 0 ----
    #pragma unroll
    for (int i = 0; i < 4; i++) {
        int slot = tid + i * 256;           // 0..1023
        int row  = slot >> 4;               // 0..63
        int c4   = (slot & 15) << 2;
        float4 vk = *(const float4*)(K + base + (size_t)row * EMBED + c4);
        float4 vv = *(const float4*)(V + base + (size_t)row * EMBED + c4);
        *(uint2*)(smh + OFF_K0 + row * HPAD + c4) =
            make_uint2(packh2(vk.x, vk.y), packh2(vk.z, vk.w));
        *(uint2*)(smh + OFF_V0 + row * HPAD + c4) =
            make_uint2(packh2(vv.x, vv.y), packh2(vv.z, vv.w));
    }
    __syncthreads();

    // ---- Q A-fragments (persist in registers) ----
    uint32_t qa[4][4];
    {
        int g2  = lane >> 3;
        int qr  = warp * 16 + (g2 & 1) * 8 + (lane & 7);
        int qcb = (g2 >> 1) * 8;
        #pragma unroll
        for (int kk = 0; kk < 4; kk++) {
            uint32_t addr = sb + (uint32_t)((OFF_Q + qr * HPAD + kk * 16 + qcb) * 2);
            ldsm_x4(qa[kk], addr);
        }
    }

    float o[8][4] = {};
    float m0 = -1e30f, m1 = -1e30f, l0 = 0.f, l1 = 0.f;

    const int NT = S >> 6;   // 32 key tiles
    float4 rk[4], rv[4];
    for (int t = 0; t < NT; t++) {
        const int cur = t & 1;
        const uint32_t kbase = sb + (uint32_t)((cur ? OFF_K1 : OFF_K0) * 2);
        const uint32_t vbase = sb + (uint32_t)((cur ? OFF_V1 : OFF_V0) * 2);

        if (t + 1 < NT) {                   // prefetch next tile into regs
            const int c0 = (t + 1) * 64;
            #pragma unroll
            for (int i = 0; i < 4; i++) {
                int slot = tid + i * 256;
                int row  = slot >> 4;
                int c4   = (slot & 15) << 2;
                rk[i] = *(const float4*)(K + base + (size_t)(c0 + row) * EMBED + c4);
                rv[i] = *(const float4*)(V + base + (size_t)(c0 + row) * EMBED + c4);
            }
        }

        // ---- S = Q' K^T (log2-units) ----
        float c[8][4];
        #pragma unroll
        for (int j = 0; j < 8; j++)
            #pragma unroll
            for (int r = 0; r < 4; r++) c[j][r] = 0.f;

        #pragma unroll
        for (int kk = 0; kk < 4; kk++) {
            #pragma unroll
            for (int j = 0; j < 8; j++) {
                uint32_t b0, b1;
                uint32_t addr = kbase + (uint32_t)(((j * 8 + (lane & 7)) * HPAD
                                 + kk * 16 + ((lane >> 3) & 1) * 8) * 2);
                ldsm_x2(b0, b1, addr);
                mma16(c[j], qa[kk], b0, b1);
            }
        }

        // ---- online softmax (rows g and g+8) ----
        float mx0 = -1e30f, mx1 = -1e30f;
        #pragma unroll
        for (int j = 0; j < 8; j++) {
            mx0 = fmaxf(mx0, fmaxf(c[j][0], c[j][1]));
            mx1 = fmaxf(mx1, fmaxf(c[j][2], c[j][3]));
        }
        mx0 = fmaxf(mx0, __shfl_xor_sync(0xffffffffu, mx0, 1));
        mx0 = fmaxf(mx0, __shfl_xor_sync(0xffffffffu, mx0, 2));
        mx1 = fmaxf(mx1, __shfl_xor_sync(0xffffffffu, mx1, 1));
        mx1 = fmaxf(mx1, __shfl_xor_sync(0xffffffffu, mx1, 2));
        float mn0 = fmaxf(m0, mx0), mn1 = fmaxf(m1, mx1);
        float a0 = exp2p(m0 - mn0), a1 = exp2p(m1 - mn1);
        m0 = mn0; m1 = mn1;

        float ps0 = 0.f, ps1 = 0.f;
        #pragma unroll
        for (int j = 0; j < 8; j++) {
            c[j][0] = exp2p(c[j][0] - mn0);
            c[j][1] = exp2p(c[j][1] - mn0);
            c[j][2] = exp2p(c[j][2] - mn1);
            c[j][3] = exp2p(c[j][3] - mn1);
            ps0 += c[j][0] + c[j][1];
            ps1 += c[j][2] + c[j][3];
        }
        l0 = l0 * a0 + ps0;
        l1 = l1 * a1 + ps1;
        #pragma unroll
        for (int dj = 0; dj < 8; dj++) {
            o[dj][0] *= a0; o[dj][1] *= a0;
            o[dj][2] *= a1; o[dj][3] *= a1;
        }

        // ---- P fragments (C-frag layout == A-frag layout) ----
        uint32_t pa[4][4];
        #pragma unroll
        for (int kk = 0; kk < 4; kk++) {
            pa[kk][0] = packh2(c[2 * kk][0],     c[2 * kk][1]);
            pa[kk][1] = packh2(c[2 * kk][2],     c[2 * kk][3]);
            pa[kk][2] = packh2(c[2 * kk + 1][0], c[2 * kk + 1][1]);
            pa[kk][3] = packh2(c[2 * kk + 1][2], c[2 * kk + 1][3]);
        }

        // ---- O += P V ----
        #pragma unroll
        for (int kk = 0; kk < 4; kk++) {
            #pragma unroll
            for (int dj = 0; dj < 8; dj++) {
                uint32_t b0, b1;
                uint32_t addr = vbase + (uint32_t)(((kk * 16 + ((lane >> 3) & 1) * 8
                                 + (lane & 7)) * HPAD + dj * 8) * 2);
                ldsm_x2t(b0, b1, addr);
                mma16(o[dj], pa[kk], b0, b1);
            }
        }

        __syncthreads();                    // all warps done with buffer cur^1
        if (t + 1 < NT) {
            const uint32_t dk = (cur ? OFF_K0 : OFF_K1);
            const uint32_t dv = (cur ? OFF_V0 : OFF_V1);
            #pragma unroll
            for (int i = 0; i < 4; i++) {
                int slot = tid + i * 256;
                int row  = slot >> 4;
                int c4   = (slot & 15) << 2;
                *(uint2*)(smh + dk + row * HPAD + c4) =
                    make_uint2(packh2(rk[i].x, rk[i].y), packh2(rk[i].z, rk[i].w));
                *(uint2*)(smh + dv + row * HPAD + c4) =
                    make_uint2(packh2(rv[i].x, rv[i].y), packh2(rv[i].z, rv[i].w));
            }
        }
        __syncthreads();
    }

    // ---- epilogue ----
    l0 += __shfl_xor_sync(0xffffffffu, l0, 1);
    l0 += __shfl_xor_sync(0xffffffffu, l0, 2);
    l1 += __shfl_xor_sync(0xffffffffu, l1, 1);
    l1 += __shfl_xor_sync(0xffffffffu, l1, 2);
    float i0 = __fdividef(1.f, l0);
    float i1 = __fdividef(1.f, l1);
    const int r0 = s0 + warp * 16 + g;
    #pragma unroll
    for (int dj = 0; dj < 8; dj++) {
        int col = dj * 8 + tig * 2;
        *(float2*)(ctx + base + (size_t)r0 * EMBED + col) =
            make_float2(o[dj][0] * i0, o[dj][1] * i0);
        *(float2*)(ctx + base + (size_t)(r0 + 8) * EMBED + col) =
            make_float2(o[dj][2] * i1, o[dj][3] * i1);
    }
}

// ===========================================================================
extern "C" void kernel_launch(void* const* d_in, const int* in_sizes, int n_in,
                              void* d_out, int out_size)
{
    const float* query = (const float*)d_in[0];
    const float* key   = (const float*)d_in[1];
    const float* value = (const float*)d_in[2];
    const float* Wq    = (const float*)d_in[3];
    const float* bq    = (const float*)d_in[4];
    const float* Wk    = (const float*)d_in[5];
    const float* bk    = (const float*)d_in[6];
    const float* Wv    = (const float*)d_in[7];
    const float* bv    = (const float*)d_in[8];
    const float* Wo    = (const float*)d_in[9];
    const float* bo    = (const float*)d_in[10];
    float* out = (float*)d_out;

    const int M = in_sizes[0] / EMBED;   // 4096
    const int B = 2;
    const int S = M / B;                 // 2048

    float *q, *k, *v, *ctx;
    cudaGetSymbolAddress((void**)&q,   g_q);
    cudaGetSymbolAddress((void**)&k,   g_k);
    cudaGetSymbolAddress((void**)&v,   g_v);
    cudaGetSymbolAddress((void**)&ctx, g_ctx);

    cudaFuncSetAttribute(gemm3_mma,
                         cudaFuncAttributeMaxDynamicSharedMemorySize, G_SMEM_BYTES);
    cudaFuncSetAttribute(flash_tc,
                         cudaFuncAttributeMaxDynamicSharedMemorySize, FLASH_SMEM);

    dim3 g3(M / 128, EMBED / 128, 3);
    gemm3_mma<<<g3, 256, G_SMEM_BYTES>>>(query, key, value,
                                         Wq, Wk, Wv, bq, bk, bv,
                                         q, k, v, M, EMBED, EMBED);

    dim3 agrid(S / 128, NHEADS, B);
    flash_tc<<<agrid, 256, FLASH_SMEM>>>(q, k, v, ctx, S);

    dim3 g1(M / 128, EMBED / 128, 1);
    gemm3_mma<<<g1, 256, G_SMEM_BYTES>>>(ctx, ctx, ctx,
                                         Wo, Wo, Wo, bo, bo, bo,
                                         out, out, out, M, EMBED, EMBED);
}

// round 5
// speedup vs baseline: 5.0611x; 1.4604x over previous
#include <cuda_runtime.h>
#include <cuda_fp16.h>
#include <cstdint>
#include <math.h>

#define EMBED   1024
#define NHEADS  16
#define MAXROWS 4096                    // B*S
#define NELEM   (MAXROWS * EMBED)       // 4M
#define WELEM   (EMBED * EMBED)         // 1M
#define QSCALE  0.18033688011112042f    // (1/8) * log2(e)

// Scratch (no cudaMalloc allowed).
__device__ float  g_qr [NELEM];         // tf32-rounded query
__device__ float  g_kr [NELEM];         // tf32-rounded key
__device__ float  g_vr [NELEM];         // tf32-rounded value
__device__ float  g_wr [4 * WELEM];     // tf32-rounded Wq|Wk|Wv|Wo
__device__ float  g_ctx[NELEM];         // attention output (tf32-rounded)
__device__ __half g_qh [NELEM];         // fp16 q (scaled by QSCALE)
__device__ __half g_kh [NELEM];         // fp16 k
__device__ __half g_vh [NELEM];         // fp16 v

// ============================ helpers ======================================
__device__ __forceinline__ uint32_t f2tf32(float x) {
    uint32_t u;
    asm("cvt.rna.tf32.f32 %0, %1;" : "=r"(u) : "f"(x));
    return u;
}
__device__ __forceinline__ uint32_t smem_u32(const void* p) {
    uint32_t a;
    asm("{ .reg .u64 t; cvta.to.shared.u64 t, %1; cvt.u32.u64 %0, t; }"
        : "=r"(a) : "l"(p));
    return a;
}
__device__ __forceinline__ uint32_t packh2(float lo, float hi) {
    __half2 h = __floats2half2_rn(lo, hi);
    return *(uint32_t*)&h;
}
// Fast exp2 on the FMA pipes (x <= 0 expected; clamped).
__device__ __forceinline__ float exp2p(float x) {
    x = fmaxf(x, -100.f);
    float r = rintf(x);
    float f = x - r;
    float p = 1.3333558e-3f;
    p = fmaf(p, f, 9.6181292e-3f);
    p = fmaf(p, f, 5.5504109e-2f);
    p = fmaf(p, f, 2.4022651e-1f);
    p = fmaf(p, f, 6.9314718e-1f);
    p = fmaf(p, f, 1.0f);
    return __int_as_float(__float_as_int(p) + ((int)r << 23));
}

#define CPA(dst, src) \
    asm volatile("cp.async.cg.shared.global [%0], [%1], 16;" :: "r"(dst), "l"(src) : "memory")
#define CP_COMMIT() asm volatile("cp.async.commit_group;" ::: "memory")
#define CP_WAIT1()  asm volatile("cp.async.wait_group 1;" ::: "memory")
#define CP_WAIT0()  asm volatile("cp.async.wait_group 0;" ::: "memory")

// m16n8k8 tf32 MMA, fp32 accumulate in place.
__device__ __forceinline__ void mma8(float* d, const uint32_t* a, const uint32_t* b) {
    asm volatile(
        "mma.sync.aligned.m16n8k8.row.col.f32.tf32.tf32.f32 "
        "{%0,%1,%2,%3},{%4,%5,%6,%7},{%8,%9},{%0,%1,%2,%3};"
        : "+f"(d[0]), "+f"(d[1]), "+f"(d[2]), "+f"(d[3])
        : "r"(a[0]), "r"(a[1]), "r"(a[2]), "r"(a[3]), "r"(b[0]), "r"(b[1]));
}
// m16n8k16 fp16 MMA, fp32 accumulate in place.
__device__ __forceinline__ void mma16(float* d, const uint32_t* a, uint32_t b0, uint32_t b1) {
    asm volatile(
        "mma.sync.aligned.m16n8k16.row.col.f32.f16.f16.f32 "
        "{%0,%1,%2,%3},{%4,%5,%6,%7},{%8,%9},{%0,%1,%2,%3};"
        : "+f"(d[0]), "+f"(d[1]), "+f"(d[2]), "+f"(d[3])
        : "r"(a[0]), "r"(a[1]), "r"(a[2]), "r"(a[3]), "r"(b0), "r"(b1));
}
__device__ __forceinline__ void ldsm_x2(uint32_t& r0, uint32_t& r1, uint32_t addr) {
    asm volatile("ldmatrix.sync.aligned.m8n8.x2.shared.b16 {%0,%1}, [%2];"
                 : "=r"(r0), "=r"(r1) : "r"(addr));
}
__device__ __forceinline__ void ldsm_x2t(uint32_t& r0, uint32_t& r1, uint32_t addr) {
    asm volatile("ldmatrix.sync.aligned.m8n8.x2.trans.shared.b16 {%0,%1}, [%2];"
                 : "=r"(r0), "=r"(r1) : "r"(addr));
}
__device__ __forceinline__ void ldsm_x4(uint32_t* r, uint32_t addr) {
    asm volatile("ldmatrix.sync.aligned.m8n8.x4.shared.b16 {%0,%1,%2,%3}, [%4];"
                 : "=r"(r[0]), "=r"(r[1]), "=r"(r[2]), "=r"(r[3]) : "r"(addr));
}

// ===========================================================================
// Prep: elementwise tf32 (rna) rounding, 4 tensors selected by blockIdx.y.
// ===========================================================================
__global__ __launch_bounds__(256) void rnd4(
    const float* __restrict__ s0, const float* __restrict__ s1,
    const float* __restrict__ s2, const float* __restrict__ s3,
    float* __restrict__ d0, float* __restrict__ d1,
    float* __restrict__ d2, float* __restrict__ d3, int n)
{
    const int z = blockIdx.y;
    const float* s = (z == 0) ? s0 : (z == 1) ? s1 : (z == 2) ? s2 : s3;
    float*       d = (z == 0) ? d0 : (z == 1) ? d1 : (z == 2) ? d2 : d3;
    int i = (blockIdx.x * 256 + threadIdx.x) * 4;
    if (i < n) {
        float4 v = *(const float4*)(s + i);
        *(uint4*)(d + i) =
            make_uint4(f2tf32(v.x), f2tf32(v.y), f2tf32(v.z), f2tf32(v.w));
    }
}

// ===========================================================================
// tf32 tensor-core NT GEMM, cp.async pipelined, 2 CTAs/SM.
// C[m,n] = sum_k A[m,k]*W[n,k] + bias[n]. All operands PRE-ROUNDED to tf32.
// 128x128 tile, K-chunk 32, 8 warps 2(m)x4(n), warp tile 64x32.
// mode 0: fp32 out (Cf). mode 1: fp16 out (H0/H1/H2), z0 scaled by QSCALE.
// ===========================================================================
#define G_SMEM_BYTES 65536   // 2 stages x (A 16KB + W 16KB)

__global__ __launch_bounds__(256, 2) void gemm_tc(
    const float* __restrict__ A0, const float* __restrict__ A1, const float* __restrict__ A2,
    const float* __restrict__ W0, const float* __restrict__ W1, const float* __restrict__ W2,
    const float* __restrict__ b0, const float* __restrict__ b1, const float* __restrict__ b2,
    float* __restrict__ Cf, __half* __restrict__ H0, __half* __restrict__ H1,
    __half* __restrict__ H2, int M, int N, int K, int mode)
{
    extern __shared__ __align__(16) char smem[];
    uint32_t* smu = (uint32_t*)smem;
    const uint32_t sb = smem_u32(smem);

    const int tid  = threadIdx.x;
    const int lane = tid & 31;
    const int wid  = tid >> 5;
    const int g    = lane >> 2;
    const int tig  = lane & 3;
    const int wm   = wid & 1;
    const int wn   = wid >> 1;
    const int bm   = blockIdx.x * 128;
    const int bn   = blockIdx.y * 128;
    const int z    = blockIdx.z;

    const float* A    = (z == 0) ? A0 : (z == 1) ? A1 : A2;
    const float* W    = (z == 0) ? W0 : (z == 1) ? W1 : W2;
    const float* bias = (z == 0) ? b0 : (z == 1) ? b1 : b2;

    const int lrow = tid >> 3;      // 0..31
    const int lc4  = tid & 7;       // float4 col 0..7

    float acc[4][4][4];
    #pragma unroll
    for (int mt = 0; mt < 4; mt++)
        #pragma unroll
        for (int nt = 0; nt < 4; nt++)
            #pragma unroll
            for (int r = 0; r < 4; r++) acc[mt][nt][r] = 0.f;

    const int NCH = K >> 5;

    // Issue one chunk's A+W tiles into stage st via cp.async (8 x 16B / thread).
    auto issue = [&](int c, int st) {
        const int k0 = c * 32;
        #pragma unroll
        for (int p = 0; p < 4; p++) {
            int r   = lrow + p * 32;
            uint32_t idx = r * 32 + ((lc4 ^ (r & 7)) << 2);
            uint32_t dA  = sb + st * 32768u + idx * 4u;
            CPA(dA,          A + (size_t)(bm + r) * K + k0 + lc4 * 4);
            CPA(dA + 16384u, W + (size_t)(bn + r) * K + k0 + lc4 * 4);
        }
    };

    issue(0, 0); CP_COMMIT();
    issue(1, 1); CP_COMMIT();

    for (int c = 0; c < NCH; c++) {
        if (c + 1 < NCH) CP_WAIT1(); else CP_WAIT0();
        __syncthreads();

        const uint32_t* sA = smu + (c & 1) * 8192;
        const uint32_t* sW = sA + 4096;

        #pragma unroll
        for (int kk = 0; kk < 4; kk++) {
            uint32_t af[4][4], bf[4][2];
            #pragma unroll
            for (int mt = 0; mt < 4; mt++) {
                int r0 = wm * 64 + mt * 16 + g;
                int r1 = r0 + 8;
                af[mt][0] = sA[r0 * 32 + (((2 * kk)     ^ (r0 & 7)) << 2) + tig];
                af[mt][1] = sA[r1 * 32 + (((2 * kk)     ^ (r1 & 7)) << 2) + tig];
                af[mt][2] = sA[r0 * 32 + (((2 * kk + 1) ^ (r0 & 7)) << 2) + tig];
                af[mt][3] = sA[r1 * 32 + (((2 * kk + 1) ^ (r1 & 7)) << 2) + tig];
            }
            #pragma unroll
            for (int nt = 0; nt < 4; nt++) {
                int rn = wn * 32 + nt * 8 + g;
                bf[nt][0] = sW[rn * 32 + (((2 * kk)     ^ (rn & 7)) << 2) + tig];
                bf[nt][1] = sW[rn * 32 + (((2 * kk + 1) ^ (rn & 7)) << 2) + tig];
            }
            #pragma unroll
            for (int mt = 0; mt < 4; mt++)
                #pragma unroll
                for (int nt = 0; nt < 4; nt++)
                    mma8(acc[mt][nt], af[mt], bf[nt]);
        }
        __syncthreads();
        if (c + 2 < NCH) { issue(c + 2, c & 1); CP_COMMIT(); }
    }

    // Epilogue.
    if (mode == 1) {
        __half* H = (z == 0) ? H0 : (z == 1) ? H1 : H2;
        const float sc = (z == 0) ? QSCALE : 1.f;
        #pragma unroll
        for (int nt = 0; nt < 4; nt++) {
            int col = bn + wn * 32 + nt * 8 + tig * 2;
            float2 bv = *(const float2*)(bias + col);
            #pragma unroll
            for (int mt = 0; mt < 4; mt++) {
                int r0 = bm + wm * 64 + mt * 16 + g;
                __half2 h0 = __floats2half2_rn((acc[mt][nt][0] + bv.x) * sc,
                                               (acc[mt][nt][1] + bv.y) * sc);
                __half2 h1 = __floats2half2_rn((acc[mt][nt][2] + bv.x) * sc,
                                               (acc[mt][nt][3] + bv.y) * sc);
                *(__half2*)(H + (size_t)r0 * N + col)       = h0;
                *(__half2*)(H + (size_t)(r0 + 8) * N + col) = h1;
            }
        }
    } else {
        #pragma unroll
        for (int nt = 0; nt < 4; nt++) {
            int col = bn + wn * 32 + nt * 8 + tig * 2;
            float2 bv = *(const float2*)(bias + col);
            #pragma unroll
            for (int mt = 0; mt < 4; mt++) {
                int r0 = bm + wm * 64 + mt * 16 + g;
                *(float2*)(Cf + (size_t)r0 * N + col) =
                    make_float2(acc[mt][nt][0] + bv.x, acc[mt][nt][1] + bv.y);
                *(float2*)(Cf + (size_t)(r0 + 8) * N + col) =
                    make_float2(acc[mt][nt][2] + bv.x, acc[mt][nt][3] + bv.y);
            }
        }
    }
}

// ===========================================================================
// fp16 tensor-core flash attention. Inputs are pre-converted fp16 (Q already
// scaled by QSCALE). cp.async double-buffered K/V; softmax in log2 domain.
// Output ctx is tf32-rounded fp32 (feeds final GEMM directly).
// ===========================================================================
#define HPAD 72
#define OFF_Q  0
#define OFF_K0 (128 * HPAD)
#define OFF_V0 (OFF_K0 + 64 * HPAD)
#define OFF_K1 (OFF_V0 + 64 * HPAD)
#define OFF_V1 (OFF_K1 + 64 * HPAD)
#define FLASH_SMEM ((OFF_V1 + 64 * HPAD) * 2)   // 55296 B

__global__ __launch_bounds__(256, 2) void flash_tc(
    const __half* __restrict__ Qh, const __half* __restrict__ Kh,
    const __half* __restrict__ Vh, float* __restrict__ ctx, int S)
{
    extern __shared__ __half smh[];
    const uint32_t sb = smem_u32(smh);

    const int tid  = threadIdx.x;
    const int lane = tid & 31;
    const int warp = tid >> 5;
    const int g    = lane >> 2;
    const int tig  = lane & 3;
    const int s0   = blockIdx.x * 128;
    const int h    = blockIdx.y;
    const int b    = blockIdx.z;
    const size_t base = ((size_t)b * S) * EMBED + (size_t)h * 64;

    const int frow = tid >> 3;          // 0..31
    const int fc8  = tid & 7;           // 16B chunk in row

    // Issue K/V tile c0 into buffers at kOff/vOff (half-units).
    auto issueKV = [&](int c0, uint32_t kOff, uint32_t vOff) {
        #pragma unroll
        for (int i = 0; i < 2; i++) {
            int row = frow + i * 32;    // 0..63
            uint32_t d = (uint32_t)(row * HPAD + fc8 * 8) * 2u;
            const size_t src = base + (size_t)(c0 + row) * EMBED + fc8 * 8;
            CPA(sb + kOff * 2u + d, Kh + src);
            CPA(sb + vOff * 2u + d, Vh + src);
        }
    };

    // Prologue: Q (4 chunks/thread) + K0/V0 as group 0, K1/V1 as group 1.
    #pragma unroll
    for (int i = 0; i < 4; i++) {
        int row = frow + i * 32;        // 0..127
        CPA(sb + (uint32_t)(OFF_Q + row * HPAD + fc8 * 8) * 2u,
            Qh + base + (size_t)(s0 + row) * EMBED + fc8 * 8);
    }
    issueKV(0, OFF_K0, OFF_V0);
    CP_COMMIT();
    issueKV(64, OFF_K1, OFF_V1);
    CP_COMMIT();

    CP_WAIT1();
    __syncthreads();

    // Q A-fragments (persist in registers).
    uint32_t qa[4][4];
    {
        int g2  = lane >> 3;
        int qr  = warp * 16 + (g2 & 1) * 8 + (lane & 7);
        int qcb = (g2 >> 1) * 8;
        #pragma unroll
        for (int kk = 0; kk < 4; kk++)
            ldsm_x4(qa[kk], sb + (uint32_t)((OFF_Q + qr * HPAD + kk * 16 + qcb) * 2));
    }

    float o[8][4] = {};
    float m0 = -1e30f, m1 = -1e30f, l0 = 0.f, l1 = 0.f;

    const int NT = S >> 6;
    for (int t = 0; t < NT; t++) {
        if (t > 0) {
            if (t + 1 < NT) CP_WAIT1(); else CP_WAIT0();
            __syncthreads();
        }
        const int cur = t & 1;
        const uint32_t kbase = sb + (uint32_t)((cur ? OFF_K1 : OFF_K0) * 2);
        const uint32_t vbase = sb + (uint32_t)((cur ? OFF_V1 : OFF_V0) * 2);

        // ---- S = Q' K^T (log2-units) ----
        float c[8][4];
        #pragma unroll
        for (int j = 0; j < 8; j++)
            #pragma unroll
            for (int r = 0; r < 4; r++) c[j][r] = 0.f;

        #pragma unroll
        for (int kk = 0; kk < 4; kk++) {
            #pragma unroll
            for (int j = 0; j < 8; j++) {
                uint32_t b0, b1;
                uint32_t addr = kbase + (uint32_t)(((j * 8 + (lane & 7)) * HPAD
                                 + kk * 16 + ((lane >> 3) & 1) * 8) * 2);
                ldsm_x2(b0, b1, addr);
                mma16(c[j], qa[kk], b0, b1);
            }
        }

        // ---- online softmax (rows g and g+8) ----
        float mx0 = -1e30f, mx1 = -1e30f;
        #pragma unroll
        for (int j = 0; j < 8; j++) {
            mx0 = fmaxf(mx0, fmaxf(c[j][0], c[j][1]));
            mx1 = fmaxf(mx1, fmaxf(c[j][2], c[j][3]));
        }
        mx0 = fmaxf(mx0, __shfl_xor_sync(0xffffffffu, mx0, 1));
        mx0 = fmaxf(mx0, __shfl_xor_sync(0xffffffffu, mx0, 2));
        mx1 = fmaxf(mx1, __shfl_xor_sync(0xffffffffu, mx1, 1));
        mx1 = fmaxf(mx1, __shfl_xor_sync(0xffffffffu, mx1, 2));
        float mn0 = fmaxf(m0, mx0), mn1 = fmaxf(m1, mx1);
        float a0 = exp2p(m0 - mn0), a1 = exp2p(m1 - mn1);
        m0 = mn0; m1 = mn1;

        float ps0 = 0.f, ps1 = 0.f;
        #pragma unroll
        for (int j = 0; j < 8; j++) {
            c[j][0] = exp2p(c[j][0] - mn0);
            c[j][1] = exp2p(c[j][1] - mn0);
            c[j][2] = exp2p(c[j][2] - mn1);
            c[j][3] = exp2p(c[j][3] - mn1);
            ps0 += c[j][0] + c[j][1];
            ps1 += c[j][2] + c[j][3];
        }
        l0 = l0 * a0 + ps0;
        l1 = l1 * a1 + ps1;
        #pragma unroll
        for (int dj = 0; dj < 8; dj++) {
            o[dj][0] *= a0; o[dj][1] *= a0;
            o[dj][2] *= a1; o[dj][3] *= a1;
        }

        // ---- P fragments (C-frag layout == A-frag layout) ----
        uint32_t pa[4][4];
        #pragma unroll
        for (int kk = 0; kk < 4; kk++) {
            pa[kk][0] = packh2(c[2 * kk][0],     c[2 * kk][1]);
            pa[kk][1] = packh2(c[2 * kk][2],     c[2 * kk][3]);
            pa[kk][2] = packh2(c[2 * kk + 1][0], c[2 * kk + 1][1]);
            pa[kk][3] = packh2(c[2 * kk + 1][2], c[2 * kk + 1][3]);
        }

        // ---- O += P V ----
        #pragma unroll
        for (int kk = 0; kk < 4; kk++) {
            #pragma unroll
            for (int dj = 0; dj < 8; dj++) {
                uint32_t b0, b1;
                uint32_t addr = vbase + (uint32_t)(((kk * 16 + ((lane >> 3) & 1) * 8
                                 + (lane & 7)) * HPAD + dj * 8) * 2);
                ldsm_x2t(b0, b1, addr);
                mma16(o[dj], pa[kk], b0, b1);
            }
        }

        __syncthreads();
        if (t + 2 < NT) {
            issueKV((t + 2) * 64, cur ? OFF_K1 : OFF_K0, cur ? OFF_V1 : OFF_V0);
            CP_COMMIT();
        }
    }

    // ---- epilogue: normalize, round to tf32, store fp32 ----
    l0 += __shfl_xor_sync(0xffffffffu, l0, 1);
    l0 += __shfl_xor_sync(0xffffffffu, l0, 2);
    l1 += __shfl_xor_sync(0xffffffffu, l1, 1);
    l1 += __shfl_xor_sync(0xffffffffu, l1, 2);
    float i0 = __fdividef(1.f, l0);
    float i1 = __fdividef(1.f, l1);
    const int r0 = s0 + warp * 16 + g;
    #pragma unroll
    for (int dj = 0; dj < 8; dj++) {
        int col = dj * 8 + tig * 2;
        uint2 v0 = make_uint2(f2tf32(o[dj][0] * i0), f2tf32(o[dj][1] * i0));
        uint2 v1 = make_uint2(f2tf32(o[dj][2] * i1), f2tf32(o[dj][3] * i1));
        *(uint2*)(ctx + base + (size_t)r0 * EMBED + col)       = v0;
        *(uint2*)(ctx + base + (size_t)(r0 + 8) * EMBED + col) = v1;
    }
}

// ===========================================================================
extern "C" void kernel_launch(void* const* d_in, const int* in_sizes, int n_in,
                              void* d_out, int out_size)
{
    const float* query = (const float*)d_in[0];
    const float* key   = (const float*)d_in[1];
    const float* value = (const float*)d_in[2];
    const float* Wq    = (const float*)d_in[3];
    const float* bq    = (const float*)d_in[4];
    const float* Wk    = (const float*)d_in[5];
    const float* bk    = (const float*)d_in[6];
    const float* Wv    = (const float*)d_in[7];
    const float* bv    = (const float*)d_in[8];
    const float* Wo    = (const float*)d_in[9];
    const float* bo    = (const float*)d_in[10];
    float* out = (float*)d_out;

    const int M = in_sizes[0] / EMBED;   // 4096
    const int B = 2;
    const int S = M / B;                 // 2048

    float  *qr, *kr, *vr, *wr, *ctx;
    __half *qh, *kh, *vh;
    cudaGetSymbolAddress((void**)&qr,  g_qr);
    cudaGetSymbolAddress((void**)&kr,  g_kr);
    cudaGetSymbolAddress((void**)&vr,  g_vr);
    cudaGetSymbolAddress((void**)&wr,  g_wr);
    cudaGetSymbolAddress((void**)&ctx, g_ctx);
    cudaGetSymbolAddress((void**)&qh,  g_qh);
    cudaGetSymbolAddress((void**)&kh,  g_kh);
    cudaGetSymbolAddress((void**)&vh,  g_vh);

    cudaFuncSetAttribute(gemm_tc,
                         cudaFuncAttributeMaxDynamicSharedMemorySize, G_SMEM_BYTES);
    cudaFuncSetAttribute(flash_tc,
                         cudaFuncAttributeMaxDynamicSharedMemorySize, FLASH_SMEM);

    // 1) pre-round inputs + weights to tf32 (rna).
    rnd4<<<dim3(NELEM / 1024, 3), 256>>>(query, key, value, query,
                                         qr, kr, vr, qr, NELEM);
    rnd4<<<dim3(WELEM / 1024, 4), 256>>>(Wq, Wk, Wv, Wo,
                                         wr, wr + WELEM, wr + 2 * WELEM, wr + 3 * WELEM,
                                         WELEM);

    // 2) Q/K/V projections -> fp16 (q pre-scaled).
    dim3 g3(M / 128, EMBED / 128, 3);
    gemm_tc<<<g3, 256, G_SMEM_BYTES>>>(qr, kr, vr,
                                       wr, wr + WELEM, wr + 2 * WELEM,
                                       bq, bk, bv,
                                       nullptr, qh, kh, vh,
                                       M, EMBED, EMBED, 1);

    // 3) flash attention -> ctx (tf32-rounded fp32).
    dim3 agrid(S / 128, NHEADS, B);
    flash_tc<<<agrid, 256, FLASH_SMEM>>>(qh, kh, vh, ctx, S);

    // 4) output projection -> out (fp32).
    dim3 g1(M / 128, EMBED / 128, 1);
    gemm_tc<<<g1, 256, G_SMEM_BYTES>>>(ctx, ctx, ctx,
                                       wr + 3 * WELEM, wr + 3 * WELEM, wr + 3 * WELEM,
                                       bo, bo, bo,
                                       out, nullptr, nullptr, nullptr,
                                       M, EMBED, EMBED, 0);
}

// round 6
// speedup vs baseline: 8.2360x; 1.6273x over previous
#include <cuda_runtime.h>
#include <cuda_fp16.h>
#include <cstdint>
#include <math.h>

#define EMBED   1024
#define NHEADS  16
#define MAXROWS 4096                    // B*S
#define NELEM   (MAXROWS * EMBED)       // 4M
#define WELEM   (EMBED * EMBED)         // 1M
#define QSCALE  0.18033688011112042f    // (1/8) * log2(e)

// Scratch (no cudaMalloc allowed).
__device__ __half g_xq[NELEM];          // fp16 query input
__device__ __half g_xk[NELEM];          // fp16 key input
__device__ __half g_xv[NELEM];          // fp16 value input
__device__ __half g_wh[4 * WELEM];      // fp16 Wq|Wk|Wv|Wo
__device__ __half g_qh[NELEM];          // fp16 q (scaled by QSCALE)
__device__ __half g_kh[NELEM];          // fp16 k
__device__ __half g_vh[NELEM];          // fp16 v
__device__ __half g_ch[NELEM];          // fp16 ctx

// ============================ helpers ======================================
__device__ __forceinline__ uint32_t smem_u32(const void* p) {
    uint32_t a;
    asm("{ .reg .u64 t; cvta.to.shared.u64 t, %1; cvt.u32.u64 %0, t; }"
        : "=r"(a) : "l"(p));
    return a;
}
__device__ __forceinline__ uint32_t packh2(float lo, float hi) {
    __half2 h = __floats2half2_rn(lo, hi);
    return *(uint32_t*)&h;
}
__device__ __forceinline__ float ex2f(float x) {   // MUFU 2^x
    float y;
    asm("ex2.approx.f32 %0, %1;" : "=f"(y) : "f"(x));
    return y;
}

#define CPA(dst, src) \
    asm volatile("cp.async.cg.shared.global [%0], [%1], 16;" :: "r"(dst), "l"(src) : "memory")
#define CP_COMMIT() asm volatile("cp.async.commit_group;" ::: "memory")
#define CP_WAIT1()  asm volatile("cp.async.wait_group 1;" ::: "memory")
#define CP_WAIT0()  asm volatile("cp.async.wait_group 0;" ::: "memory")

// m16n8k16 fp16 MMA, fp32 accumulate in place.
__device__ __forceinline__ void mma16(float* d, const uint32_t* a, uint32_t b0, uint32_t b1) {
    asm volatile(
        "mma.sync.aligned.m16n8k16.row.col.f32.f16.f16.f32 "
        "{%0,%1,%2,%3},{%4,%5,%6,%7},{%8,%9},{%0,%1,%2,%3};"
        : "+f"(d[0]), "+f"(d[1]), "+f"(d[2]), "+f"(d[3])
        : "r"(a[0]), "r"(a[1]), "r"(a[2]), "r"(a[3]), "r"(b0), "r"(b1));
}
__device__ __forceinline__ void ldsm_x2t(uint32_t& r0, uint32_t& r1, uint32_t addr) {
    asm volatile("ldmatrix.sync.aligned.m8n8.x2.trans.shared.b16 {%0,%1}, [%2];"
                 : "=r"(r0), "=r"(r1) : "r"(addr));
}
__device__ __forceinline__ void ldsm_x4(uint32_t* r, uint32_t addr) {
    asm volatile("ldmatrix.sync.aligned.m8n8.x4.shared.b16 {%0,%1,%2,%3}, [%4];"
                 : "=r"(r[0]), "=r"(r[1]), "=r"(r[2]), "=r"(r[3]) : "r"(addr));
}
__device__ __forceinline__ void ldsm_x4t(uint32_t* r, uint32_t addr) {
    asm volatile("ldmatrix.sync.aligned.m8n8.x4.trans.shared.b16 {%0,%1,%2,%3}, [%4];"
                 : "=r"(r[0]), "=r"(r[1]), "=r"(r[2]), "=r"(r[3]) : "r"(addr));
}

// ===========================================================================
// Prep: fp32 -> fp16, 4 tensors selected by blockIdx.y, 8 elems/thread.
// ===========================================================================
__global__ __launch_bounds__(256) void cvt4(
    const float* __restrict__ s0, const float* __restrict__ s1,
    const float* __restrict__ s2, const float* __restrict__ s3,
    __half* __restrict__ d0, __half* __restrict__ d1,
    __half* __restrict__ d2, __half* __restrict__ d3, int n)
{
    const int z = blockIdx.y;
    const float* s = (z == 0) ? s0 : (z == 1) ? s1 : (z == 2) ? s2 : s3;
    __half*      d = (z == 0) ? d0 : (z == 1) ? d1 : (z == 2) ? d2 : d3;
    int i = (blockIdx.x * 256 + threadIdx.x) * 8;
    if (i < n) {
        float4 a = *(const float4*)(s + i);
        float4 b = *(const float4*)(s + i + 4);
        uint4 o;
        o.x = packh2(a.x, a.y);
        o.y = packh2(a.z, a.w);
        o.z = packh2(b.x, b.y);
        o.w = packh2(b.z, b.w);
        *(uint4*)(d + i) = o;
    }
}

// ===========================================================================
// fp16 tensor-core NT GEMM: C[m,n] = sum_k A[m,k]*W[n,k] + bias[n].
// 128x128 tile, K-chunk 64 halves, 2-stage cp.async, 8 warps 2(m)x4(n),
// warp tile 64x32, m16n8k16, ldmatrix.x4 fragment loads.
// smem rows: 64 halves (128B) as 8x16B chunks, chunk XOR (row&7) swizzle.
// mode 0: fp32 out. mode 1: fp16 out (z0 scaled by QSCALE).
// ===========================================================================
#define G_SMEM_BYTES 65536   // 2 stages x (A 16KB + W 16KB)

__global__ __launch_bounds__(256, 2) void gemm_h(
    const __half* __restrict__ A0, const __half* __restrict__ A1, const __half* __restrict__ A2,
    const __half* __restrict__ W0, const __half* __restrict__ W1, const __half* __restrict__ W2,
    const float* __restrict__ b0, const float* __restrict__ b1, const float* __restrict__ b2,
    float* __restrict__ Cf, __half* __restrict__ H0, __half* __restrict__ H1,
    __half* __restrict__ H2, int M, int N, int K, int mode)
{
    extern __shared__ __align__(16) char smem[];
    const uint32_t sb = smem_u32(smem);

    const int tid  = threadIdx.x;
    const int lane = tid & 31;
    const int wid  = tid >> 5;
    const int g    = lane >> 2;
    const int tig  = lane & 3;
    const int wm   = wid & 1;
    const int wn   = wid >> 1;
    const int bm   = blockIdx.x * 128;
    const int bn   = blockIdx.y * 128;
    const int z    = blockIdx.z;

    const __half* A    = (z == 0) ? A0 : (z == 1) ? A1 : A2;
    const __half* W    = (z == 0) ? W0 : (z == 1) ? W1 : W2;
    const float*  bias = (z == 0) ? b0 : (z == 1) ? b1 : b2;

    const int lrow = tid >> 3;      // 0..31
    const int lc8  = tid & 7;       // 16B chunk 0..7

    float acc[4][4][4];
    #pragma unroll
    for (int mt = 0; mt < 4; mt++)
        #pragma unroll
        for (int nt = 0; nt < 4; nt++)
            #pragma unroll
            for (int r = 0; r < 4; r++) acc[mt][nt][r] = 0.f;

    const int NCH = K >> 6;         // 16 chunks of 64 halves

    auto issue = [&](int c, int st) {
        const int k0 = c * 64;
        #pragma unroll
        for (int p = 0; p < 4; p++) {
            int r = lrow + p * 32;
            uint32_t dA = sb + st * 32768u + (uint32_t)(r * 128 + ((lc8 ^ (r & 7)) << 4));
            CPA(dA,          A + (size_t)(bm + r) * K + k0 + lc8 * 8);
            CPA(dA + 16384u, W + (size_t)(bn + r) * K + k0 + lc8 * 8);
        }
    };

    issue(0, 0); CP_COMMIT();
    issue(1, 1); CP_COMMIT();

    // ldsm lane decomposition (hoisted).
    const int l7  = lane & 7;
    const int l8  = (lane >> 3) & 1;
    const int l16 = lane >> 4;

    for (int c = 0; c < NCH; c++) {
        if (c + 1 < NCH) CP_WAIT1(); else CP_WAIT0();
        __syncthreads();

        const uint32_t stg = sb + (uint32_t)((c & 1) * 32768);

        #pragma unroll
        for (int kk = 0; kk < 4; kk++) {
            uint32_t af[4][4], bf[4][2];
            #pragma unroll
            for (int mt = 0; mt < 4; mt++) {
                int row = wm * 64 + mt * 16 + l8 * 8 + l7;
                int c8  = kk * 2 + l16;
                ldsm_x4(af[mt], stg + (uint32_t)(row * 128 + ((c8 ^ (row & 7)) << 4)));
            }
            #pragma unroll
            for (int ntp = 0; ntp < 2; ntp++) {
                int row = wn * 32 + ntp * 16 + l16 * 8 + l7;
                int c8  = kk * 2 + l8;
                uint32_t r4[4];
                ldsm_x4(r4, stg + 16384u + (uint32_t)(row * 128 + ((c8 ^ (row & 7)) << 4)));
                bf[2 * ntp][0]     = r4[0];
                bf[2 * ntp][1]     = r4[1];
                bf[2 * ntp + 1][0] = r4[2];
                bf[2 * ntp + 1][1] = r4[3];
            }
            #pragma unroll
            for (int mt = 0; mt < 4; mt++)
                #pragma unroll
                for (int nt = 0; nt < 4; nt++)
                    mma16(acc[mt][nt], af[mt], bf[nt][0], bf[nt][1]);
        }
        __syncthreads();
        if (c + 2 < NCH) { issue(c + 2, c & 1); CP_COMMIT(); }
    }

    // Epilogue.
    if (mode == 1) {
        __half* H = (z == 0) ? H0 : (z == 1) ? H1 : H2;
        const float sc = (z == 0) ? QSCALE : 1.f;
        #pragma unroll
        for (int nt = 0; nt < 4; nt++) {
            int col = bn + wn * 32 + nt * 8 + tig * 2;
            float2 bv = *(const float2*)(bias + col);
            #pragma unroll
            for (int mt = 0; mt < 4; mt++) {
                int r0 = bm + wm * 64 + mt * 16 + g;
                *(uint32_t*)(H + (size_t)r0 * N + col) =
                    packh2((acc[mt][nt][0] + bv.x) * sc, (acc[mt][nt][1] + bv.y) * sc);
                *(uint32_t*)(H + (size_t)(r0 + 8) * N + col) =
                    packh2((acc[mt][nt][2] + bv.x) * sc, (acc[mt][nt][3] + bv.y) * sc);
            }
        }
    } else {
        #pragma unroll
        for (int nt = 0; nt < 4; nt++) {
            int col = bn + wn * 32 + nt * 8 + tig * 2;
            float2 bv = *(const float2*)(bias + col);
            #pragma unroll
            for (int mt = 0; mt < 4; mt++) {
                int r0 = bm + wm * 64 + mt * 16 + g;
                *(float2*)(Cf + (size_t)r0 * N + col) =
                    make_float2(acc[mt][nt][0] + bv.x, acc[mt][nt][1] + bv.y);
                *(float2*)(Cf + (size_t)(r0 + 8) * N + col) =
                    make_float2(acc[mt][nt][2] + bv.x, acc[mt][nt][3] + bv.y);
            }
        }
    }
}

// ===========================================================================
// fp16 tensor-core flash attention.
// New vs R5: ldmatrix.x4 loads; exp via MUFU ex2.approx.f32; row-sum l
// computed by the tensor core via a ones-column at V col 64 (dj=8 group,
// HPAD padding region). Output ctx is fp16.
// ===========================================================================
#define HPAD 72
#define OFF_Q  0
#define OFF_K0 (128 * HPAD)
#define OFF_V0 (OFF_K0 + 64 * HPAD)
#define OFF_K1 (OFF_V0 + 64 * HPAD)
#define OFF_V1 (OFF_K1 + 64 * HPAD)
#define FLASH_SMEM ((OFF_V1 + 64 * HPAD) * 2)   // 55296 B

__global__ __launch_bounds__(256, 2) void flash_tc(
    const __half* __restrict__ Qh, const __half* __restrict__ Kh,
    const __half* __restrict__ Vh, __half* __restrict__ ctx, int S)
{
    extern __shared__ __half smh[];
    const uint32_t sb = smem_u32(smh);

    const int tid  = threadIdx.x;
    const int lane = tid & 31;
    const int warp = tid >> 5;
    const int g    = lane >> 2;
    const int tig  = lane & 3;
    const int s0   = blockIdx.x * 128;
    const int h    = blockIdx.y;
    const int b    = blockIdx.z;
    const size_t base = ((size_t)b * S) * EMBED + (size_t)h * 64;

    const int frow = tid >> 3;
    const int fc8  = tid & 7;

    auto issueKV = [&](int c0, uint32_t kOff, uint32_t vOff) {
        #pragma unroll
        for (int i = 0; i < 2; i++) {
            int row = frow + i * 32;
            uint32_t d = (uint32_t)(row * HPAD + fc8 * 8) * 2u;
            const size_t src = base + (size_t)(c0 + row) * EMBED + fc8 * 8;
            CPA(sb + kOff * 2u + d, Kh + src);
            CPA(sb + vOff * 2u + d, Vh + src);
        }
    };

    // Prologue: Q + K0/V0 (group 0), K1/V1 (group 1).
    #pragma unroll
    for (int i = 0; i < 4; i++) {
        int row = frow + i * 32;
        CPA(sb + (uint32_t)(OFF_Q + row * HPAD + fc8 * 8) * 2u,
            Qh + base + (size_t)(s0 + row) * EMBED + fc8 * 8);
    }
    issueKV(0, OFF_K0, OFF_V0);
    CP_COMMIT();
    issueKV(64, OFF_K1, OFF_V1);
    CP_COMMIT();

    // Ones-column init: V cols 64..71 = [1,0,0,0,0,0,0,0] (both buffers).
    if (tid < 128) {
        int row = tid & 63;
        uint32_t off = (uint32_t)(((tid >> 6) ? OFF_V1 : OFF_V0) + row * HPAD + 64);
        *(uint4*)(smh + off) = make_uint4(0x00003C00u, 0u, 0u, 0u);
    }

    CP_WAIT1();
    __syncthreads();

    const int l7  = lane & 7;
    const int l8  = (lane >> 3) & 1;
    const int l16 = lane >> 4;

    // Q A-fragments (persist in registers).
    uint32_t qa[4][4];
    {
        int qr = warp * 16 + l8 * 8 + l7;
        #pragma unroll
        for (int kk = 0; kk < 4; kk++)
            ldsm_x4(qa[kk], sb + (uint32_t)((OFF_Q + qr * HPAD + kk * 16 + l16 * 8) * 2));
    }

    float o[9][4] = {};   // o[8] = row-sum accumulator (V ones-column)
    float m0 = -1e30f, m1 = -1e30f;

    const int NT = S >> 6;
    for (int t = 0; t < NT; t++) {
        if (t > 0) {
            if (t + 1 < NT) CP_WAIT1(); else CP_WAIT0();
            __syncthreads();
        }
        const int cur = t & 1;
        const uint32_t kbase = sb + (uint32_t)((cur ? OFF_K1 : OFF_K0) * 2);
        const uint32_t vbase = sb + (uint32_t)((cur ? OFF_V1 : OFF_V0) * 2);

        // ---- S = Q' K^T (log2-units) ----
        float c[8][4];
        #pragma unroll
        for (int j = 0; j < 8; j++)
            #pragma unroll
            for (int r = 0; r < 4; r++) c[j][r] = 0.f;

        #pragma unroll
        for (int kk = 0; kk < 4; kk++) {
            #pragma unroll
            for (int jp = 0; jp < 4; jp++) {
                uint32_t r4[4];
                uint32_t addr = kbase + (uint32_t)((((2 * jp + l16) * 8 + l7) * HPAD
                                 + kk * 16 + l8 * 8) * 2);
                ldsm_x4(r4, addr);
                mma16(c[2 * jp],     qa[kk], r4[0], r4[1]);
                mma16(c[2 * jp + 1], qa[kk], r4[2], r4[3]);
            }
        }

        // ---- online softmax (rows g and g+8) ----
        float mx0 = -1e30f, mx1 = -1e30f;
        #pragma unroll
        for (int j = 0; j < 8; j++) {
            mx0 = fmaxf(mx0, fmaxf(c[j][0], c[j][1]));
            mx1 = fmaxf(mx1, fmaxf(c[j][2], c[j][3]));
        }
        mx0 = fmaxf(mx0, __shfl_xor_sync(0xffffffffu, mx0, 1));
        mx0 = fmaxf(mx0, __shfl_xor_sync(0xffffffffu, mx0, 2));
        mx1 = fmaxf(mx1, __shfl_xor_sync(0xffffffffu, mx1, 1));
        mx1 = fmaxf(mx1, __shfl_xor_sync(0xffffffffu, mx1, 2));
        float mn0 = fmaxf(m0, mx0), mn1 = fmaxf(m1, mx1);
        float a0 = ex2f(m0 - mn0), a1 = ex2f(m1 - mn1);
        m0 = mn0; m1 = mn1;

        // P fragments: exp via MUFU, packed straight into A-frag layout.
        uint32_t pa[4][4];
        #pragma unroll
        for (int kk = 0; kk < 4; kk++) {
            pa[kk][0] = packh2(ex2f(c[2 * kk][0] - mn0),     ex2f(c[2 * kk][1] - mn0));
            pa[kk][1] = packh2(ex2f(c[2 * kk][2] - mn1),     ex2f(c[2 * kk][3] - mn1));
            pa[kk][2] = packh2(ex2f(c[2 * kk + 1][0] - mn0), ex2f(c[2 * kk + 1][1] - mn0));
            pa[kk][3] = packh2(ex2f(c[2 * kk + 1][2] - mn1), ex2f(c[2 * kk + 1][3] - mn1));
        }

        // Rescale O (incl. the l accumulator o[8]).
        #pragma unroll
        for (int dj = 0; dj < 9; dj++) {
            o[dj][0] *= a0; o[dj][1] *= a0;
            o[dj][2] *= a1; o[dj][3] *= a1;
        }

        // ---- O += P V (dj=8 accumulates row sums via ones-column) ----
        #pragma unroll
        for (int kk = 0; kk < 4; kk++) {
            uint32_t rowa = (uint32_t)((kk * 16 + l8 * 8 + l7) * HPAD);
            #pragma unroll
            for (int djp = 0; djp < 4; djp++) {
                uint32_t r4[4];
                ldsm_x4t(r4, vbase + (rowa + (2 * djp + l16) * 8) * 2u);
                mma16(o[2 * djp],     pa[kk], r4[0], r4[1]);
                mma16(o[2 * djp + 1], pa[kk], r4[2], r4[3]);
            }
            uint32_t b0, b1;
            ldsm_x2t(b0, b1, vbase + (rowa + 64) * 2u);
            mma16(o[8], pa[kk], b0, b1);
        }

        __syncthreads();
        if (t + 2 < NT) {
            issueKV((t + 2) * 64, cur ? OFF_K1 : OFF_K0, cur ? OFF_V1 : OFF_V0);
            CP_COMMIT();
        }
    }

    // ---- epilogue: l lives in o[8][0]/o[8][2] of the tig==0 lane ----
    float l0 = __shfl_sync(0xffffffffu, o[8][0], lane & 28);
    float l1 = __shfl_sync(0xffffffffu, o[8][2], lane & 28);
    float i0 = __fdividef(1.f, l0);
    float i1 = __fdividef(1.f, l1);
    const int r0 = s0 + warp * 16 + g;
    #pragma unroll
    for (int dj = 0; dj < 8; dj++) {
        int col = dj * 8 + tig * 2;
        *(uint32_t*)(ctx + base + (size_t)r0 * EMBED + col) =
            packh2(o[dj][0] * i0, o[dj][1] * i0);
        *(uint32_t*)(ctx + base + (size_t)(r0 + 8) * EMBED + col) =
            packh2(o[dj][2] * i1, o[dj][3] * i1);
    }
}

// ===========================================================================
extern "C" void kernel_launch(void* const* d_in, const int* in_sizes, int n_in,
                              void* d_out, int out_size)
{
    const float* query = (const float*)d_in[0];
    const float* key   = (const float*)d_in[1];
    const float* value = (const float*)d_in[2];
    const float* Wq    = (const float*)d_in[3];
    const float* bq    = (const float*)d_in[4];
    const float* Wk    = (const float*)d_in[5];
    const float* bk    = (const float*)d_in[6];
    const float* Wv    = (const float*)d_in[7];
    const float* bv    = (const float*)d_in[8];
    const float* Wo    = (const float*)d_in[9];
    const float* bo    = (const float*)d_in[10];
    float* out = (float*)d_out;

    const int M = in_sizes[0] / EMBED;   // 4096
    const int B = 2;
    const int S = M / B;                 // 2048

    __half *xq, *xk, *xv, *wh, *qh, *kh, *vh, *ch;
    cudaGetSymbolAddress((void**)&xq, g_xq);
    cudaGetSymbolAddress((void**)&xk, g_xk);
    cudaGetSymbolAddress((void**)&xv, g_xv);
    cudaGetSymbolAddress((void**)&wh, g_wh);
    cudaGetSymbolAddress((void**)&qh, g_qh);
    cudaGetSymbolAddress((void**)&kh, g_kh);
    cudaGetSymbolAddress((void**)&vh, g_vh);
    cudaGetSymbolAddress((void**)&ch, g_ch);

    cudaFuncSetAttribute(gemm_h,
                         cudaFuncAttributeMaxDynamicSharedMemorySize, G_SMEM_BYTES);
    cudaFuncSetAttribute(flash_tc,
                         cudaFuncAttributeMaxDynamicSharedMemorySize, FLASH_SMEM);

    // 1) fp32 -> fp16 conversion of inputs and weights.
    cvt4<<<dim3(NELEM / 2048, 3), 256>>>(query, key, value, query,
                                         xq, xk, xv, xq, NELEM);
    cvt4<<<dim3(WELEM / 2048, 4), 256>>>(Wq, Wk, Wv, Wo,
                                         wh, wh + WELEM, wh + 2 * WELEM, wh + 3 * WELEM,
                                         WELEM);

    // 2) Q/K/V projections -> fp16 (q pre-scaled by QSCALE).
    dim3 g3(M / 128, EMBED / 128, 3);
    gemm_h<<<g3, 256, G_SMEM_BYTES>>>(xq, xk, xv,
                                      wh, wh + WELEM, wh + 2 * WELEM,
                                      bq, bk, bv,
                                      nullptr, qh, kh, vh,
                                      M, EMBED, EMBED, 1);

    // 3) flash attention -> ctx (fp16).
    dim3 agrid(S / 128, NHEADS, B);
    flash_tc<<<agrid, 256, FLASH_SMEM>>>(qh, kh, vh, ch, S);

    // 4) output projection -> out (fp32).
    dim3 g1(M / 128, EMBED / 128, 1);
    gemm_h<<<g1, 256, G_SMEM_BYTES>>>(ch, ch, ch,
                                      wh + 3 * WELEM, wh + 3 * WELEM, wh + 3 * WELEM,
                                      bo, bo, bo,
                                      out, nullptr, nullptr, nullptr,
                                      M, EMBED, EMBED, 0);
}

// round 7
// speedup vs baseline: 8.6827x; 1.0542x over previous
#include <cuda_runtime.h>
#include <cuda_fp16.h>
#include <cstdint>
#include <math.h>

#define EMBED   1024
#define NHEADS  16
#define MAXROWS 4096                    // B*S
#define NELEM   (MAXROWS * EMBED)       // 4M
#define WELEM   (EMBED * EMBED)         // 1M
#define QSCALE  0.18033688011112042f    // (1/8) * log2(e)

// Scratch (no cudaMalloc allowed).
__device__ __half g_xq[NELEM];          // fp16 query input
__device__ __half g_xk[NELEM];          // fp16 key input
__device__ __half g_xv[NELEM];          // fp16 value input
__device__ __half g_wh[4 * WELEM];      // fp16 Wq|Wk|Wv|Wo
__device__ __half g_qh[NELEM];          // fp16 q (scaled by QSCALE)
__device__ __half g_kh[NELEM];          // fp16 k
__device__ __half g_vh[NELEM];          // fp16 v
__device__ __half g_ch[NELEM];          // fp16 ctx

// ============================ helpers ======================================
__device__ __forceinline__ uint32_t smem_u32(const void* p) {
    uint32_t a;
    asm("{ .reg .u64 t; cvta.to.shared.u64 t, %1; cvt.u32.u64 %0, t; }"
        : "=r"(a) : "l"(p));
    return a;
}
__device__ __forceinline__ uint32_t packh2(float lo, float hi) {
    __half2 h = __floats2half2_rn(lo, hi);
    return *(uint32_t*)&h;
}
__device__ __forceinline__ float ex2f(float x) {   // MUFU 2^x (fp32)
    float y;
    asm("ex2.approx.f32 %0, %1;" : "=f"(y) : "f"(x));
    return y;
}
__device__ __forceinline__ uint32_t hexp2x2(uint32_t x) {  // MUFU 2^x on half2
    uint32_t y;
    asm("ex2.approx.f16x2 %0, %1;" : "=r"(y) : "r"(x));
    return y;
}

#define CPA(dst, src) \
    asm volatile("cp.async.cg.shared.global [%0], [%1], 16;" :: "r"(dst), "l"(src) : "memory")
#define CP_COMMIT() asm volatile("cp.async.commit_group;" ::: "memory")
#define CP_WAIT1()  asm volatile("cp.async.wait_group 1;" ::: "memory")
#define CP_WAIT0()  asm volatile("cp.async.wait_group 0;" ::: "memory")

// m16n8k16 fp16 MMA, fp32 accumulate in place.
__device__ __forceinline__ void mma16(float* d, const uint32_t* a, uint32_t b0, uint32_t b1) {
    asm volatile(
        "mma.sync.aligned.m16n8k16.row.col.f32.f16.f16.f32 "
        "{%0,%1,%2,%3},{%4,%5,%6,%7},{%8,%9},{%0,%1,%2,%3};"
        : "+f"(d[0]), "+f"(d[1]), "+f"(d[2]), "+f"(d[3])
        : "r"(a[0]), "r"(a[1]), "r"(a[2]), "r"(a[3]), "r"(b0), "r"(b1));
}
__device__ __forceinline__ void ldsm_x2t(uint32_t& r0, uint32_t& r1, uint32_t addr) {
    asm volatile("ldmatrix.sync.aligned.m8n8.x2.trans.shared.b16 {%0,%1}, [%2];"
                 : "=r"(r0), "=r"(r1) : "r"(addr));
}
__device__ __forceinline__ void ldsm_x4(uint32_t* r, uint32_t addr) {
    asm volatile("ldmatrix.sync.aligned.m8n8.x4.shared.b16 {%0,%1,%2,%3}, [%4];"
                 : "=r"(r[0]), "=r"(r[1]), "=r"(r[2]), "=r"(r[3]) : "r"(addr));
}
__device__ __forceinline__ void ldsm_x4t(uint32_t* r, uint32_t addr) {
    asm volatile("ldmatrix.sync.aligned.m8n8.x4.trans.shared.b16 {%0,%1,%2,%3}, [%4];"
                 : "=r"(r[0]), "=r"(r[1]), "=r"(r[2]), "=r"(r[3]) : "r"(addr));
}

// ===========================================================================
// Prep: fp32 -> fp16 for all 7 tensors in one launch (blockIdx.y selects).
// ===========================================================================
__global__ __launch_bounds__(256) void cvt7(
    const float* __restrict__ s0, const float* __restrict__ s1,
    const float* __restrict__ s2, const float* __restrict__ s3,
    const float* __restrict__ s4, const float* __restrict__ s5,
    const float* __restrict__ s6,
    __half* __restrict__ d0, __half* __restrict__ d1, __half* __restrict__ d2,
    __half* __restrict__ d3, __half* __restrict__ d4, __half* __restrict__ d5,
    __half* __restrict__ d6, int n_big, int n_small)
{
    const int z = blockIdx.y;
    const float* s; __half* d; int n;
    switch (z) {
        case 0: s = s0; d = d0; n = n_big;   break;
        case 1: s = s1; d = d1; n = n_big;   break;
        case 2: s = s2; d = d2; n = n_big;   break;
        case 3: s = s3; d = d3; n = n_small; break;
        case 4: s = s4; d = d4; n = n_small; break;
        case 5: s = s5; d = d5; n = n_small; break;
        default: s = s6; d = d6; n = n_small; break;
    }
    int i = (blockIdx.x * 256 + threadIdx.x) * 8;
    if (i < n) {
        float4 a = *(const float4*)(s + i);
        float4 b = *(const float4*)(s + i + 4);
        uint4 o;
        o.x = packh2(a.x, a.y);
        o.y = packh2(a.z, a.w);
        o.z = packh2(b.x, b.y);
        o.w = packh2(b.z, b.w);
        *(uint4*)(d + i) = o;
    }
}

// ===========================================================================
// fp16 tensor-core NT GEMM: C[m,n] = sum_k A[m,k]*W[n,k] + bias[n].
// 128x128 tile, K-chunk 64 halves, 3-stage cp.async ring, ONE barrier per
// chunk (issue c+2 right after wait/sync). 8 warps 2(m)x4(n), m16n8k16,
// ldmatrix.x4. mode 0: fp32 out. mode 1: fp16 out (z0 scaled by QSCALE).
// ===========================================================================
#define G_SMEM_BYTES 98304   // 3 stages x (A 16KB + W 16KB)

__global__ __launch_bounds__(256, 2) void gemm_h(
    const __half* __restrict__ A0, const __half* __restrict__ A1, const __half* __restrict__ A2,
    const __half* __restrict__ W0, const __half* __restrict__ W1, const __half* __restrict__ W2,
    const float* __restrict__ b0, const float* __restrict__ b1, const float* __restrict__ b2,
    float* __restrict__ Cf, __half* __restrict__ H0, __half* __restrict__ H1,
    __half* __restrict__ H2, int M, int N, int K, int mode)
{
    extern __shared__ __align__(16) char smem[];
    const uint32_t sb = smem_u32(smem);

    const int tid  = threadIdx.x;
    const int lane = tid & 31;
    const int wid  = tid >> 5;
    const int g    = lane >> 2;
    const int tig  = lane & 3;
    const int wm   = wid & 1;
    const int wn   = wid >> 1;
    const int bm   = blockIdx.x * 128;
    const int bn   = blockIdx.y * 128;
    const int z    = blockIdx.z;

    const __half* A    = (z == 0) ? A0 : (z == 1) ? A1 : A2;
    const __half* W    = (z == 0) ? W0 : (z == 1) ? W1 : W2;
    const float*  bias = (z == 0) ? b0 : (z == 1) ? b1 : b2;

    const int lrow = tid >> 3;      // 0..31
    const int lc8  = tid & 7;       // 16B chunk 0..7

    float acc[4][4][4];
    #pragma unroll
    for (int mt = 0; mt < 4; mt++)
        #pragma unroll
        for (int nt = 0; nt < 4; nt++)
            #pragma unroll
            for (int r = 0; r < 4; r++) acc[mt][nt][r] = 0.f;

    const int NCH = K >> 6;         // 16 chunks of 64 halves

    auto issue = [&](int c, int st) {
        const int k0 = c * 64;
        #pragma unroll
        for (int p = 0; p < 4; p++) {
            int r = lrow + p * 32;
            uint32_t dA = sb + st * 32768u + (uint32_t)(r * 128 + ((lc8 ^ (r & 7)) << 4));
            CPA(dA,          A + (size_t)(bm + r) * K + k0 + lc8 * 8);
            CPA(dA + 16384u, W + (size_t)(bn + r) * K + k0 + lc8 * 8);
        }
    };

    issue(0, 0); CP_COMMIT();
    issue(1, 1); CP_COMMIT();

    const int l7  = lane & 7;
    const int l8  = (lane >> 3) & 1;
    const int l16 = lane >> 4;

    int st_c  = 0;   // stage of chunk c
    int st_n2 = 2;   // stage for chunk c+2

    for (int c = 0; c < NCH; c++) {
        if (c + 1 < NCH) CP_WAIT1(); else CP_WAIT0();
        __syncthreads();
        if (c + 2 < NCH) { issue(c + 2, st_n2); CP_COMMIT(); }

        const uint32_t stg = sb + (uint32_t)(st_c * 32768);

        #pragma unroll
        for (int kk = 0; kk < 4; kk++) {
            uint32_t af[4][4], bf[4][2];
            #pragma unroll
            for (int mt = 0; mt < 4; mt++) {
                int row = wm * 64 + mt * 16 + l8 * 8 + l7;
                int c8  = kk * 2 + l16;
                ldsm_x4(af[mt], stg + (uint32_t)(row * 128 + ((c8 ^ (row & 7)) << 4)));
            }
            #pragma unroll
            for (int ntp = 0; ntp < 2; ntp++) {
                int row = wn * 32 + ntp * 16 + l16 * 8 + l7;
                int c8  = kk * 2 + l8;
                uint32_t r4[4];
                ldsm_x4(r4, stg + 16384u + (uint32_t)(row * 128 + ((c8 ^ (row & 7)) << 4)));
                bf[2 * ntp][0]     = r4[0];
                bf[2 * ntp][1]     = r4[1];
                bf[2 * ntp + 1][0] = r4[2];
                bf[2 * ntp + 1][1] = r4[3];
            }
            #pragma unroll
            for (int mt = 0; mt < 4; mt++)
                #pragma unroll
                for (int nt = 0; nt < 4; nt++)
                    mma16(acc[mt][nt], af[mt], bf[nt][0], bf[nt][1]);
        }
        st_c  = (st_c  == 2) ? 0 : st_c + 1;
        st_n2 = (st_n2 == 2) ? 0 : st_n2 + 1;
    }

    // Epilogue.
    if (mode == 1) {
        __half* H = (z == 0) ? H0 : (z == 1) ? H1 : H2;
        const float sc = (z == 0) ? QSCALE : 1.f;
        #pragma unroll
        for (int nt = 0; nt < 4; nt++) {
            int col = bn + wn * 32 + nt * 8 + tig * 2;
            float2 bv = *(const float2*)(bias + col);
            #pragma unroll
            for (int mt = 0; mt < 4; mt++) {
                int r0 = bm + wm * 64 + mt * 16 + g;
                *(uint32_t*)(H + (size_t)r0 * N + col) =
                    packh2((acc[mt][nt][0] + bv.x) * sc, (acc[mt][nt][1] + bv.y) * sc);
                *(uint32_t*)(H + (size_t)(r0 + 8) * N + col) =
                    packh2((acc[mt][nt][2] + bv.x) * sc, (acc[mt][nt][3] + bv.y) * sc);
            }
        }
    } else {
        #pragma unroll
        for (int nt = 0; nt < 4; nt++) {
            int col = bn + wn * 32 + nt * 8 + tig * 2;
            float2 bv = *(const float2*)(bias + col);
            #pragma unroll
            for (int mt = 0; mt < 4; mt++) {
                int r0 = bm + wm * 64 + mt * 16 + g;
                *(float2*)(Cf + (size_t)r0 * N + col) =
                    make_float2(acc[mt][nt][0] + bv.x, acc[mt][nt][1] + bv.y);
                *(float2*)(Cf + (size_t)(r0 + 8) * N + col) =
                    make_float2(acc[mt][nt][2] + bv.x, acc[mt][nt][3] + bv.y);
            }
        }
    }
}

// ===========================================================================
// fp16 tensor-core flash attention.
// New vs R6: 3-stage K/V ring with ONE barrier per tile; exp via packed
// ex2.approx.f16x2 landing directly in the P A-fragment; row-sum l via
// ones-column at V col 64. Output ctx fp16.
// ===========================================================================
#define HPAD 72
#define OFF_Q  0
#define KV_STG (2 * 64 * HPAD)                   // halves per K+V stage
#define OFF_K(s) (128 * HPAD + (s) * KV_STG)
#define OFF_V(s) (OFF_K(s) + 64 * HPAD)
#define FLASH_SMEM ((128 * HPAD + 3 * KV_STG) * 2)   // 73728 B

__global__ __launch_bounds__(256, 2) void flash_tc(
    const __half* __restrict__ Qh, const __half* __restrict__ Kh,
    const __half* __restrict__ Vh, __half* __restrict__ ctx, int S)
{
    extern __shared__ __half smh[];
    const uint32_t sb = smem_u32(smh);

    const int tid  = threadIdx.x;
    const int lane = tid & 31;
    const int warp = tid >> 5;
    const int g    = lane >> 2;
    const int tig  = lane & 3;
    const int s0   = blockIdx.x * 128;
    const int h    = blockIdx.y;
    const int b    = blockIdx.z;
    const size_t base = ((size_t)b * S) * EMBED + (size_t)h * 64;

    const int frow = tid >> 3;
    const int fc8  = tid & 7;

    auto issueKV = [&](int c0, int st) {
        const uint32_t kOff = (uint32_t)OFF_K(st);
        const uint32_t vOff = (uint32_t)OFF_V(st);
        #pragma unroll
        for (int i = 0; i < 2; i++) {
            int row = frow + i * 32;
            uint32_t d = (uint32_t)(row * HPAD + fc8 * 8) * 2u;
            const size_t src = base + (size_t)(c0 + row) * EMBED + fc8 * 8;
            CPA(sb + kOff * 2u + d, Kh + src);
            CPA(sb + vOff * 2u + d, Vh + src);
        }
    };

    // Prologue: Q + K/V tile 0 (group 0), K/V tile 1 (group 1).
    #pragma unroll
    for (int i = 0; i < 4; i++) {
        int row = frow + i * 32;
        CPA(sb + (uint32_t)(OFF_Q + row * HPAD + fc8 * 8) * 2u,
            Qh + base + (size_t)(s0 + row) * EMBED + fc8 * 8);
    }
    issueKV(0, 0);
    CP_COMMIT();
    issueKV(64, 1);
    CP_COMMIT();

    // Ones-column init: V cols 64..71 = [1,0,0,0,0,0,0,0] (all 3 stages).
    if (tid < 192) {
        int row = tid & 63;
        int st  = tid >> 6;
        *(uint4*)(smh + (uint32_t)(OFF_V(st) + row * HPAD + 64)) =
            make_uint4(0x00003C00u, 0u, 0u, 0u);
    }

    CP_WAIT1();
    __syncthreads();

    const int l7  = lane & 7;
    const int l8  = (lane >> 3) & 1;
    const int l16 = lane >> 4;

    // Q A-fragments (persist in registers).
    uint32_t qa[4][4];
    {
        int qr = warp * 16 + l8 * 8 + l7;
        #pragma unroll
        for (int kk = 0; kk < 4; kk++)
            ldsm_x4(qa[kk], sb + (uint32_t)((OFF_Q + qr * HPAD + kk * 16 + l16 * 8) * 2));
    }

    float o[9][4] = {};   // o[8] = row-sum accumulator (V ones-column)
    float m0 = -1e30f, m1 = -1e30f;

    const int NT = S >> 6;
    int st_c  = 0;   // stage of tile t
    int st_n2 = 2;   // stage for tile t+2

    for (int t = 0; t < NT; t++) {
        if (t > 0) {
            if (t + 1 < NT) CP_WAIT1(); else CP_WAIT0();
            __syncthreads();
        }
        if (t + 2 < NT) { issueKV((t + 2) * 64, st_n2); CP_COMMIT(); }

        const uint32_t kbase = sb + (uint32_t)(OFF_K(st_c) * 2);
        const uint32_t vbase = sb + (uint32_t)(OFF_V(st_c) * 2);

        // ---- S = Q' K^T (log2-units) ----
        float c[8][4];
        #pragma unroll
        for (int j = 0; j < 8; j++)
            #pragma unroll
            for (int r = 0; r < 4; r++) c[j][r] = 0.f;

        #pragma unroll
        for (int kk = 0; kk < 4; kk++) {
            #pragma unroll
            for (int jp = 0; jp < 4; jp++) {
                uint32_t r4[4];
                uint32_t addr = kbase + (uint32_t)((((2 * jp + l16) * 8 + l7) * HPAD
                                 + kk * 16 + l8 * 8) * 2);
                ldsm_x4(r4, addr);
                mma16(c[2 * jp],     qa[kk], r4[0], r4[1]);
                mma16(c[2 * jp + 1], qa[kk], r4[2], r4[3]);
            }
        }

        // ---- online softmax (rows g and g+8) ----
        float mx0 = -1e30f, mx1 = -1e30f;
        #pragma unroll
        for (int j = 0; j < 8; j++) {
            mx0 = fmaxf(mx0, fmaxf(c[j][0], c[j][1]));
            mx1 = fmaxf(mx1, fmaxf(c[j][2], c[j][3]));
        }
        mx0 = fmaxf(mx0, __shfl_xor_sync(0xffffffffu, mx0, 1));
        mx0 = fmaxf(mx0, __shfl_xor_sync(0xffffffffu, mx0, 2));
        mx1 = fmaxf(mx1, __shfl_xor_sync(0xffffffffu, mx1, 1));
        mx1 = fmaxf(mx1, __shfl_xor_sync(0xffffffffu, mx1, 2));
        float mn0 = fmaxf(m0, mx0), mn1 = fmaxf(m1, mx1);
        float a0 = ex2f(m0 - mn0), a1 = ex2f(m1 - mn1);
        m0 = mn0; m1 = mn1;

        // P fragments: packed fp16 exp straight into A-frag layout.
        uint32_t pa[4][4];
        #pragma unroll
        for (int kk = 0; kk < 4; kk++) {
            pa[kk][0] = hexp2x2(packh2(c[2 * kk][0] - mn0,     c[2 * kk][1] - mn0));
            pa[kk][1] = hexp2x2(packh2(c[2 * kk][2] - mn1,     c[2 * kk][3] - mn1));
            pa[kk][2] = hexp2x2(packh2(c[2 * kk + 1][0] - mn0, c[2 * kk + 1][1] - mn0));
            pa[kk][3] = hexp2x2(packh2(c[2 * kk + 1][2] - mn1, c[2 * kk + 1][3] - mn1));
        }

        // Rescale O (incl. the l accumulator o[8]).
        #pragma unroll
        for (int dj = 0; dj < 9; dj++) {
            o[dj][0] *= a0; o[dj][1] *= a0;
            o[dj][2] *= a1; o[dj][3] *= a1;
        }

        // ---- O += P V (dj=8 accumulates row sums via ones-column) ----
        #pragma unroll
        for (int kk = 0; kk < 4; kk++) {
            uint32_t rowa = (uint32_t)((kk * 16 + l8 * 8 + l7) * HPAD);
            #pragma unroll
            for (int djp = 0; djp < 4; djp++) {
                uint32_t r4[4];
                ldsm_x4t(r4, vbase + (rowa + (2 * djp + l16) * 8) * 2u);
                mma16(o[2 * djp],     pa[kk], r4[0], r4[1]);
                mma16(o[2 * djp + 1], pa[kk], r4[2], r4[3]);
            }
            uint32_t b0, b1;
            ldsm_x2t(b0, b1, vbase + (rowa + 64) * 2u);
            mma16(o[8], pa[kk], b0, b1);
        }

        st_c  = (st_c  == 2) ? 0 : st_c + 1;
        st_n2 = (st_n2 == 2) ? 0 : st_n2 + 1;
    }

    // ---- epilogue: l lives in o[8][0]/o[8][2] of the tig==0 lane ----
    float l0 = __shfl_sync(0xffffffffu, o[8][0], lane & 28);
    float l1 = __shfl_sync(0xffffffffu, o[8][2], lane & 28);
    float i0 = __fdividef(1.f, l0);
    float i1 = __fdividef(1.f, l1);
    const int r0 = s0 + warp * 16 + g;
    #pragma unroll
    for (int dj = 0; dj < 8; dj++) {
        int col = dj * 8 + tig * 2;
        *(uint32_t*)(ctx + base + (size_t)r0 * EMBED + col) =
            packh2(o[dj][0] * i0, o[dj][1] * i0);
        *(uint32_t*)(ctx + base + (size_t)(r0 + 8) * EMBED + col) =
            packh2(o[dj][2] * i1, o[dj][3] * i1);
    }
}

// ===========================================================================
extern "C" void kernel_launch(void* const* d_in, const int* in_sizes, int n_in,
                              void* d_out, int out_size)
{
    const float* query = (const float*)d_in[0];
    const float* key   = (const float*)d_in[1];
    const float* value = (const float*)d_in[2];
    const float* Wq    = (const float*)d_in[3];
    const float* bq    = (const float*)d_in[4];
    const float* Wk    = (const float*)d_in[5];
    const float* bk    = (const float*)d_in[6];
    const float* Wv    = (const float*)d_in[7];
    const float* bv    = (const float*)d_in[8];
    const float* Wo    = (const float*)d_in[9];
    const float* bo    = (const float*)d_in[10];
    float* out = (float*)d_out;

    const int M = in_sizes[0] / EMBED;   // 4096
    const int B = 2;
    const int S = M / B;                 // 2048

    __half *xq, *xk, *xv, *wh, *qh, *kh, *vh, *ch;
    cudaGetSymbolAddress((void**)&xq, g_xq);
    cudaGetSymbolAddress((void**)&xk, g_xk);
    cudaGetSymbolAddress((void**)&xv, g_xv);
    cudaGetSymbolAddress((void**)&wh, g_wh);
    cudaGetSymbolAddress((void**)&qh, g_qh);
    cudaGetSymbolAddress((void**)&kh, g_kh);
    cudaGetSymbolAddress((void**)&vh, g_vh);
    cudaGetSymbolAddress((void**)&ch, g_ch);

    cudaFuncSetAttribute(gemm_h,
                         cudaFuncAttributeMaxDynamicSharedMemorySize, G_SMEM_BYTES);
    cudaFuncSetAttribute(flash_tc,
                         cudaFuncAttributeMaxDynamicSharedMemorySize, FLASH_SMEM);

    // 1) fp32 -> fp16 conversion of inputs and weights (one launch).
    cvt7<<<dim3(NELEM / 2048, 7), 256>>>(
        query, key, value, Wq, Wk, Wv, Wo,
        xq, xk, xv, wh, wh + WELEM, wh + 2 * WELEM, wh + 3 * WELEM,
        NELEM, WELEM);

    // 2) Q/K/V projections -> fp16 (q pre-scaled by QSCALE).
    dim3 g3(M / 128, EMBED / 128, 3);
    gemm_h<<<g3, 256, G_SMEM_BYTES>>>(xq, xk, xv,
                                      wh, wh + WELEM, wh + 2 * WELEM,
                                      bq, bk, bv,
                                      nullptr, qh, kh, vh,
                                      M, EMBED, EMBED, 1);

    // 3) flash attention -> ctx (fp16).
    dim3 agrid(S / 128, NHEADS, B);
    flash_tc<<<agrid, 256, FLASH_SMEM>>>(qh, kh, vh, ch, S);

    // 4) output projection -> out (fp32).
    dim3 g1(M / 128, EMBED / 128, 1);
    gemm_h<<<g1, 256, G_SMEM_BYTES>>>(ch, ch, ch,
                                      wh + 3 * WELEM, wh + 3 * WELEM, wh + 3 * WELEM,
                                      bo, bo, bo,
                                      out, nullptr, nullptr, nullptr,
                                      M, EMBED, EMBED, 0);
}